// round 1
// baseline (speedup 1.0000x reference)
#include <cuda_runtime.h>
#include <cstddef>

#define DM 768
#define DI 1536
#define DS 16
#define DR 48
#define KCONV 4
#define BB 2
#define LL 1024
#define TT (BB*LL)          // 2048 tokens
#define NPROJ 80            // 48 dt + 16 B + 16 C

// ---------------- scratch (device globals; no allocation allowed) ----------
__device__ float g_xs[TT*DI];
__device__ float g_z[TT*DI];
__device__ float g_xc[2][TT*DI];
__device__ float g_proj[2][TT*NPROJ];
__device__ float g_delta[2][TT*DI];
__device__ float g_y[2][TT*DI];
__device__ float g_ycomb[TT*DI];
__device__ float g_wproj[2][NPROJ*DI];

// ---------------- helpers ----------------
__device__ __forceinline__ float siluf(float x) {
    return x / (1.0f + __expf(-x));
}
__device__ __forceinline__ float softplusf(float x) {
    return (x > 20.0f) ? x : log1pf(__expf(x));
}

// ---------------- generic NT SGEMM: C[M,N] = A[M,K] * B[N,K]^T ------------
// 64x64 tile, BK=16, 256 threads, 4x4 per thread, reg-prefetch double buffer.
// Assumes K % 16 == 0, N % 4 == 0, 16B-aligned rows (lda/ldb/ldc % 4 == 0).
__global__ __launch_bounds__(256)
void gemm_nt(const float* __restrict__ A, int lda,
             const float* __restrict__ B, int ldb,
             float* __restrict__ C, int ldc,
             int M, int N, int K,
             const float* __restrict__ bias, int act)
{
    __shared__ float As[16][68];
    __shared__ float Bs[16][68];

    const int tid = threadIdx.x;
    const int bm = blockIdx.y * 64;
    const int bn = blockIdx.x * 64;

    const int lr = tid >> 2;            // 0..63 row within tile (load)
    const int lc = (tid & 3) << 2;      // 0,4,8,12 col within k-tile (load)
    const int tm = (tid >> 4) << 2;     // 0..60 compute row offset
    const int tn = (tid & 15) << 2;     // 0..60 compute col offset

    float acc[4][4];
#pragma unroll
    for (int i = 0; i < 4; i++)
#pragma unroll
        for (int j = 0; j < 4; j++) acc[i][j] = 0.0f;

    const int ntiles = K >> 4;
    const bool aok = (bm + lr) < M;
    const bool bok = (bn + lr) < N;
    const float* Ap = A + (size_t)(bm + lr) * lda + lc;
    const float* Bp = B + (size_t)(bn + lr) * ldb + lc;

    float4 ar = aok ? *(const float4*)Ap : make_float4(0, 0, 0, 0);
    float4 br = bok ? *(const float4*)Bp : make_float4(0, 0, 0, 0);

    for (int t = 0; t < ntiles; ++t) {
        As[lc + 0][lr] = ar.x; As[lc + 1][lr] = ar.y;
        As[lc + 2][lr] = ar.z; As[lc + 3][lr] = ar.w;
        Bs[lc + 0][lr] = br.x; Bs[lc + 1][lr] = br.y;
        Bs[lc + 2][lr] = br.z; Bs[lc + 3][lr] = br.w;
        __syncthreads();

        if (t + 1 < ntiles) {
            int off = (t + 1) << 4;
            ar = aok ? *(const float4*)(Ap + off) : make_float4(0, 0, 0, 0);
            br = bok ? *(const float4*)(Bp + off) : make_float4(0, 0, 0, 0);
        }

#pragma unroll
        for (int k = 0; k < 16; ++k) {
            float4 av = *(const float4*)&As[k][tm];
            float4 bv = *(const float4*)&Bs[k][tn];
            float aa[4] = { av.x, av.y, av.z, av.w };
            float bb[4] = { bv.x, bv.y, bv.z, bv.w };
#pragma unroll
            for (int i = 0; i < 4; i++)
#pragma unroll
                for (int j = 0; j < 4; j++)
                    acc[i][j] = fmaf(aa[i], bb[j], acc[i][j]);
        }
        __syncthreads();
    }

#pragma unroll
    for (int i = 0; i < 4; i++) {
        int row = bm + tm + i;
        if (row >= M) continue;
        int col = bn + tn;
        if (col >= N) continue;
        float4 v = make_float4(acc[i][0], acc[i][1], acc[i][2], acc[i][3]);
        if (bias) {
            v.x += bias[col + 0]; v.y += bias[col + 1];
            v.z += bias[col + 2]; v.w += bias[col + 3];
        }
        if (act == 1) {
            v.x = softplusf(v.x); v.y = softplusf(v.y);
            v.z = softplusf(v.z); v.w = softplusf(v.w);
        }
        *(float4*)(C + (size_t)row * ldc + col) = v;
    }
}

// ---------------- concat projection weights into [80,1536] per dir --------
__global__ void concat_wproj(const float* __restrict__ Wdt, const float* __restrict__ WB,
                             const float* __restrict__ WC,
                             const float* __restrict__ Wdtb, const float* __restrict__ WBb,
                             const float* __restrict__ WCb,
                             float* __restrict__ w0, float* __restrict__ w1)
{
    int i = blockIdx.x * blockDim.x + threadIdx.x;
    if (i >= NPROJ * DI) return;
    int r = i / DI, c = i % DI;
    float vf, vb;
    if (r < 48)      { vf = Wdt[r * DI + c];        vb = Wdtb[r * DI + c]; }
    else if (r < 64) { vf = WB[(r - 48) * DI + c];  vb = WBb[(r - 48) * DI + c]; }
    else             { vf = WC[(r - 64) * DI + c];  vb = WCb[(r - 64) * DI + c]; }
    w0[i] = vf; w1[i] = vb;
}

// ---------------- causal depthwise conv (K=4) + silu, both directions -----
__global__ void conv_silu_kernel(const float* __restrict__ xs,
                                 const float* __restrict__ cw, const float* __restrict__ cb,
                                 const float* __restrict__ cwb, const float* __restrict__ cbb,
                                 float* __restrict__ xcf, float* __restrict__ xcbk)
{
    int idx = blockIdx.x * blockDim.x + threadIdx.x;
    if (idx >= TT * DI) return;
    int d = idx % DI;
    int t = (idx / DI) % LL;
    int b = idx / (DI * LL);
    const float* xb = xs + (size_t)b * LL * DI + d;

    // forward: xc[t] = sum_k xs[t-3+k] * w[k]
    float accf = cb[d];
    if (t >= 3) accf = fmaf(xb[(size_t)(t - 3) * DI], cw[d * 4 + 0], accf);
    if (t >= 2) accf = fmaf(xb[(size_t)(t - 2) * DI], cw[d * 4 + 1], accf);
    if (t >= 1) accf = fmaf(xb[(size_t)(t - 1) * DI], cw[d * 4 + 2], accf);
    accf = fmaf(xb[(size_t)t * DI], cw[d * 4 + 3], accf);
    xcf[idx] = siluf(accf);

    // backward (scan-time t, underlying seq reversed): xs_b[tau]=xs[L-1-tau]
    int base = (LL - 1) - t;
    float accb = cbb[d];
    if (t >= 3) accb = fmaf(xb[(size_t)(base + 3) * DI], cwb[d * 4 + 0], accb);
    if (t >= 2) accb = fmaf(xb[(size_t)(base + 2) * DI], cwb[d * 4 + 1], accb);
    if (t >= 1) accb = fmaf(xb[(size_t)(base + 1) * DI], cwb[d * 4 + 2], accb);
    accb = fmaf(xb[(size_t)base * DI], cwb[d * 4 + 3], accb);
    xcbk[idx] = siluf(accb);
}

// ---------------- selective scan: 16 state lanes per channel --------------
// grid.x = dir(2) * b(2) * dgroup(96), block = 256 threads (8 warps, 16 d).
__global__ __launch_bounds__(256)
void scan_kernel(const float* __restrict__ xc0, const float* __restrict__ xc1,
                 const float* __restrict__ dl0, const float* __restrict__ dl1,
                 const float* __restrict__ pj0, const float* __restrict__ pj1,
                 const float* __restrict__ Alog0, const float* __restrict__ Alog1,
                 const float* __restrict__ Dp0, const float* __restrict__ Dp1,
                 float* __restrict__ y0, float* __restrict__ y1)
{
    int bid = blockIdx.x;
    int dgroup = bid % 96;
    int b = (bid / 96) % BB;
    int dir = bid / (96 * BB);

    const float* xc = dir ? xc1 : xc0;
    const float* dl = dir ? dl1 : dl0;
    const float* pj = dir ? pj1 : pj0;
    const float* Alog = dir ? Alog1 : Alog0;
    const float* Dp = dir ? Dp1 : Dp0;
    float* y = dir ? y1 : y0;

    int lane = threadIdx.x & 31;
    int w = threadIdx.x >> 5;
    int n = lane & 15;
    int d = dgroup * 16 + w * 2 + (lane >> 4);

    const float* xcp = xc + (size_t)b * LL * DI + d;
    const float* dlp = dl + (size_t)b * LL * DI + d;
    const float* pjB = pj + (size_t)b * LL * NPROJ + 48 + n;
    const float* pjC = pj + (size_t)b * LL * NPROJ + 64 + n;
    float* yp = y + (size_t)b * LL * DI + d;

    const float A = -__expf(Alog[d * DS + n]);
    const float Dd = Dp[d];

    float h = 0.0f;
    float dv = dlp[0], xv = xcp[0], Bv = pjB[0], Cv = pjC[0];

    for (int t = 0; t < LL; ++t) {
        float dv2 = 0.f, xv2 = 0.f, Bv2 = 0.f, Cv2 = 0.f;
        if (t + 1 < LL) {   // prefetch next step
            dv2 = dlp[(size_t)(t + 1) * DI];
            xv2 = xcp[(size_t)(t + 1) * DI];
            Bv2 = pjB[(size_t)(t + 1) * NPROJ];
            Cv2 = pjC[(size_t)(t + 1) * NPROJ];
        }
        float dA = __expf(dv * A);
        h = fmaf(dA, h, dv * xv * Bv);
        float p = h * Cv;
        p += __shfl_xor_sync(0xffffffffu, p, 1);
        p += __shfl_xor_sync(0xffffffffu, p, 2);
        p += __shfl_xor_sync(0xffffffffu, p, 4);
        p += __shfl_xor_sync(0xffffffffu, p, 8);
        if (n == 0) yp[(size_t)t * DI] = fmaf(Dd, xv, p);
        dv = dv2; xv = xv2; Bv = Bv2; Cv = Cv2;
    }
}

// ---------------- combine: 0.5 * silu(z) * (y_f + reverse(y_b)) -----------
__global__ void combine_kernel(const float* __restrict__ z,
                               const float* __restrict__ yf,
                               const float* __restrict__ yb,
                               float* __restrict__ out)
{
    int idx = blockIdx.x * blockDim.x + threadIdx.x;
    if (idx >= TT * DI) return;
    int d = idx % DI;
    int l = (idx / DI) % LL;
    int b = idx / (DI * LL);
    float zz = z[idx];
    float s = zz / (1.0f + __expf(-zz));
    float v = yf[idx] + yb[((size_t)b * LL + (LL - 1 - l)) * DI + d];
    out[idx] = 0.5f * s * v;
}

// ---------------- launch ---------------------------------------------------
extern "C" void kernel_launch(void* const* d_in, const int* in_sizes, int n_in,
                              void* d_out, int out_size)
{
    const float* x        = (const float*)d_in[0];
    const float* W_in_s   = (const float*)d_in[1];
    const float* W_in_g   = (const float*)d_in[2];
    const float* conv_w   = (const float*)d_in[3];
    const float* conv_b   = (const float*)d_in[4];
    const float* conv_w_b = (const float*)d_in[5];
    const float* conv_b_b = (const float*)d_in[6];
    const float* W_dt     = (const float*)d_in[7];
    const float* W_B      = (const float*)d_in[8];
    const float* W_C      = (const float*)d_in[9];
    const float* dtW      = (const float*)d_in[10];
    const float* dtb      = (const float*)d_in[11];
    const float* A_log    = (const float*)d_in[12];
    const float* Dp       = (const float*)d_in[13];
    const float* W_dt_b   = (const float*)d_in[14];
    const float* W_B_b    = (const float*)d_in[15];
    const float* W_C_b    = (const float*)d_in[16];
    const float* dtW_b    = (const float*)d_in[17];
    const float* dtb_b    = (const float*)d_in[18];
    const float* A_log_b  = (const float*)d_in[19];
    const float* Dp_b     = (const float*)d_in[20];
    const float* W_out    = (const float*)d_in[21];
    float* out = (float*)d_out;

    float *p_xs, *p_z, *p_xc, *p_proj, *p_delta, *p_y, *p_yc, *p_wp;
    cudaGetSymbolAddress((void**)&p_xs, g_xs);
    cudaGetSymbolAddress((void**)&p_z, g_z);
    cudaGetSymbolAddress((void**)&p_xc, g_xc);
    cudaGetSymbolAddress((void**)&p_proj, g_proj);
    cudaGetSymbolAddress((void**)&p_delta, g_delta);
    cudaGetSymbolAddress((void**)&p_y, g_y);
    cudaGetSymbolAddress((void**)&p_yc, g_ycomb);
    cudaGetSymbolAddress((void**)&p_wp, g_wproj);

    float* xc0 = p_xc;               float* xc1 = p_xc + (size_t)TT * DI;
    float* pj0 = p_proj;             float* pj1 = p_proj + (size_t)TT * NPROJ;
    float* dl0 = p_delta;            float* dl1 = p_delta + (size_t)TT * DI;
    float* y0  = p_y;                float* y1  = p_y + (size_t)TT * DI;
    float* wp0 = p_wp;               float* wp1 = p_wp + (size_t)NPROJ * DI;

    const int EW = 256;
    const int nEW = (TT * DI + EW - 1) / EW;

    // 1) concat projection weights
    concat_wproj<<<(NPROJ * DI + 255) / 256, 256>>>(
        W_dt, W_B, W_C, W_dt_b, W_B_b, W_C_b, wp0, wp1);

    // 2) input projections: xs = x @ W_in_s^T, z = x @ W_in_g^T
    {
        dim3 grid(DI / 64, TT / 64);
        gemm_nt<<<grid, 256>>>(x, DM, W_in_s, DM, p_xs, DI, TT, DI, DM, nullptr, 0);
        gemm_nt<<<grid, 256>>>(x, DM, W_in_g, DM, p_z, DI, TT, DI, DM, nullptr, 0);
    }

    // 3) causal conv + silu (both directions)
    conv_silu_kernel<<<nEW, EW>>>(p_xs, conv_w, conv_b, conv_w_b, conv_b_b, xc0, xc1);

    // 4) fused dt/B/C projection per direction: [T,80] = xc @ Wproj^T
    {
        dim3 grid((NPROJ + 63) / 64, TT / 64);
        gemm_nt<<<grid, 256>>>(xc0, DI, wp0, DI, pj0, NPROJ, TT, NPROJ, DI, nullptr, 0);
        gemm_nt<<<grid, 256>>>(xc1, DI, wp1, DI, pj1, NPROJ, TT, NPROJ, DI, nullptr, 0);
    }

    // 5) delta = softplus(dt_low @ dtW^T + dtb) per direction (K=48, lda=80)
    {
        dim3 grid(DI / 64, TT / 64);
        gemm_nt<<<grid, 256>>>(pj0, NPROJ, dtW, DR, dl0, DI, TT, DI, DR, dtb, 1);
        gemm_nt<<<grid, 256>>>(pj1, NPROJ, dtW_b, DR, dl1, DI, TT, DI, DR, dtb_b, 1);
    }

    // 6) selective scan (both directions in one launch)
    scan_kernel<<<2 * BB * (DI / 16), 256>>>(
        xc0, xc1, dl0, dl1, pj0, pj1, A_log, A_log_b, Dp, Dp_b, y0, y1);

    // 7) combine with gates and reverse backward stream
    combine_kernel<<<nEW, EW>>>(p_z, y0, y1, p_yc);

    // 8) output projection: out = ycomb @ W_out^T
    {
        dim3 grid(DM / 64, TT / 64);
        gemm_nt<<<grid, 256>>>(p_yc, DI, W_out, DI, out, DM, TT, DM, DI, nullptr, 0);
    }
}

// round 3
// speedup vs baseline: 1.1217x; 1.1217x over previous
#include <cuda_runtime.h>
#include <cuda_bf16.h>
#include <cstdint>
#include <cstddef>

#define DM 768
#define DI 1536
#define DS 16
#define DR 48
#define BB 2
#define LL 1024
#define TT (BB*LL)
#define NPROJ 80
#define NXZ 3072          // xs(1536) + z(1536) fused in-proj
#define K3_IN  2304       // 3*768
#define K3_BIG 4608       // 3*1536
#define K3_DT  192        // 3*64 (48 padded to 64)

// ======================= scratch (device globals) =======================
__device__ __align__(128) float g_xz[TT*NXZ];
__device__ __align__(128) __nv_bfloat16 g_x3[(size_t)TT*K3_IN];
__device__ __align__(128) __nv_bfloat16 g_Wcat3[(size_t)NXZ*K3_IN];
__device__ __align__(128) float g_xc[2][TT*DI];
__device__ __align__(128) __nv_bfloat16 g_xc3[2][(size_t)TT*K3_BIG];
__device__ __align__(128) float g_wproj[2][NPROJ*DI];
__device__ __align__(128) __nv_bfloat16 g_wproj3[2][(size_t)NPROJ*K3_BIG];
__device__ __align__(128) float g_pj[2][TT*NPROJ];
__device__ __align__(128) __nv_bfloat16 g_pj3[2][(size_t)TT*K3_DT];
__device__ __align__(128) __nv_bfloat16 g_dtW3[2][(size_t)DI*K3_DT];
__device__ __align__(128) float g_delta[2][TT*DI];
__device__ __align__(128) float g_y[2][TT*DI];
__device__ __align__(128) __nv_bfloat16 g_yc3[(size_t)TT*K3_BIG];
__device__ __align__(128) __nv_bfloat16 g_Wout3[(size_t)DM*K3_BIG];

__device__ __forceinline__ float siluf(float x) { return x / (1.0f + __expf(-x)); }
__device__ __forceinline__ float softplusf(float x) {
    return (x > 20.0f) ? x : log1pf(__expf(x));
}
__device__ __forceinline__ void split3(float v, __nv_bfloat16& hi, __nv_bfloat16& lo) {
    hi = __float2bfloat16(v);
    lo = __float2bfloat16(v - __bfloat162float(hi));
}

// =============== bf16-triple conversion: fp32[rows,K] -> bf16[rows,3*Kseg]
// isA: segs {hi, lo, hi};  !isA (B-side): segs {hi, hi, lo}
// sum over 3K of A3*B3 = hi*hi + lo*hi + hi*lo  (compensated bf16x3 product)
__global__ void conv3_kernel(const float* __restrict__ src, int lds, int Kreal,
                             int Kseg, __nv_bfloat16* __restrict__ dst, int isA,
                             int total)
{
    int idx = blockIdx.x * blockDim.x + threadIdx.x;
    if (idx >= total) return;
    int r = idx / Kseg, k = idx - r * Kseg;
    float v = (k < Kreal) ? src[(size_t)r * lds + k] : 0.0f;
    __nv_bfloat16 hi, lo; split3(v, hi, lo);
    size_t base = (size_t)r * 3 * Kseg;
    if (isA) { dst[base + k] = hi; dst[base + Kseg + k] = lo; dst[base + 2*Kseg + k] = hi; }
    else     { dst[base + k] = hi; dst[base + Kseg + k] = hi; dst[base + 2*Kseg + k] = lo; }
}

// =============== concat dt/B/C weights into [80,1536] per dir =============
__global__ void concat_wproj(const float* __restrict__ Wdt, const float* __restrict__ WB,
                             const float* __restrict__ WC,
                             const float* __restrict__ Wdtb, const float* __restrict__ WBb,
                             const float* __restrict__ WCb,
                             float* __restrict__ w0, float* __restrict__ w1)
{
    int i = blockIdx.x * blockDim.x + threadIdx.x;
    if (i >= NPROJ * DI) return;
    int r = i / DI, c = i % DI;
    float vf, vb;
    if (r < 48)      { vf = Wdt[r * DI + c];        vb = Wdtb[r * DI + c]; }
    else if (r < 64) { vf = WB[(r - 48) * DI + c];  vb = WBb[(r - 48) * DI + c]; }
    else             { vf = WC[(r - 64) * DI + c];  vb = WCb[(r - 64) * DI + c]; }
    w0[i] = vf; w1[i] = vb;
}

// ======================= mma.sync bf16 NT GEMM ============================
// C[z][2048, Nreal] = A3[z][2048, K3] * B3[z][Npad, K3]^T  (bf16 in, fp32 acc)
// 128x128x32 tile, 8 warps (2x4), 64x32 per warp, m16n8k16 HMMA.
#define GBK 32
#define GLDS 40                 // padded row stride (bf16): 32 + 8
#define GBUF (128*GLDS)         // bf16 elements per tile buffer

__device__ __forceinline__ void ldsm4(uint32_t* r, uint32_t addr) {
    asm volatile("ldmatrix.sync.aligned.m8n8.x4.shared.b16 {%0,%1,%2,%3}, [%4];"
                 : "=r"(r[0]), "=r"(r[1]), "=r"(r[2]), "=r"(r[3]) : "r"(addr));
}
__device__ __forceinline__ void mma16816(float* d, const uint32_t* a,
                                         uint32_t b0, uint32_t b1) {
    asm volatile("mma.sync.aligned.m16n8k16.row.col.f32.bf16.bf16.f32 "
                 "{%0,%1,%2,%3}, {%4,%5,%6,%7}, {%8,%9}, {%0,%1,%2,%3};"
                 : "+f"(d[0]), "+f"(d[1]), "+f"(d[2]), "+f"(d[3])
                 : "r"(a[0]), "r"(a[1]), "r"(a[2]), "r"(a[3]), "r"(b0), "r"(b1));
}

__global__ __launch_bounds__(256, 1)
void gemm_mma(const __nv_bfloat16* __restrict__ A0, const __nv_bfloat16* __restrict__ A1,
              const __nv_bfloat16* __restrict__ B0, const __nv_bfloat16* __restrict__ B1,
              float* __restrict__ C0, float* __restrict__ C1,
              int ldc, int K3, int Nreal,
              const float* __restrict__ bias0, const float* __restrict__ bias1, int act)
{
    __shared__ __nv_bfloat16 sA[2][GBUF];
    __shared__ __nv_bfloat16 sB[2][GBUF];

    const int z = blockIdx.z;
    const __nv_bfloat16* A = z ? A1 : A0;
    const __nv_bfloat16* B = z ? B1 : B0;
    float* C = z ? C1 : C0;
    const float* bias = z ? bias1 : bias0;

    const int tid = threadIdx.x;
    const int lane = tid & 31;
    const int wid = tid >> 5;
    const int bm0 = blockIdx.y * 128;
    const int bn0 = blockIdx.x * 128;
    const int wm = (wid >> 2) * 64;     // 0 or 64
    const int wn = (wid & 3) * 32;      // 0,32,64,96

    const uint32_t aBase = (uint32_t)__cvta_generic_to_shared(&sA[0][0]);
    const uint32_t bBase = (uint32_t)__cvta_generic_to_shared(&sB[0][0]);
    const int lr = lane & 15, lh = lane >> 4;

    float acc[4][4][4];
#pragma unroll
    for (int i = 0; i < 4; i++)
#pragma unroll
        for (int j = 0; j < 4; j++)
#pragma unroll
            for (int v = 0; v < 4; v++) acc[i][j][v] = 0.0f;

    const int nt = K3 / GBK;
    const int row0 = tid >> 2;          // 0..63
    const int row1 = row0 + 64;
    const int ch = tid & 3;             // 16B chunk within 64B row

    uint4 ra0, ra1, rb0, rb1;
    auto gload = [&](int t) {
        size_t koff = (size_t)t * GBK + ch * 8;
        ra0 = *(const uint4*)(A + (size_t)(bm0 + row0) * K3 + koff);
        ra1 = *(const uint4*)(A + (size_t)(bm0 + row1) * K3 + koff);
        rb0 = (bn0 + row0 < Nreal) ? *(const uint4*)(B + (size_t)(bn0 + row0) * K3 + koff)
                                   : make_uint4(0u, 0u, 0u, 0u);
        rb1 = (bn0 + row1 < Nreal) ? *(const uint4*)(B + (size_t)(bn0 + row1) * K3 + koff)
                                   : make_uint4(0u, 0u, 0u, 0u);
    };
    auto sstore = [&](int p) {
        *(uint4*)(&sA[p][row0 * GLDS + ch * 8]) = ra0;
        *(uint4*)(&sA[p][row1 * GLDS + ch * 8]) = ra1;
        *(uint4*)(&sB[p][row0 * GLDS + ch * 8]) = rb0;
        *(uint4*)(&sB[p][row1 * GLDS + ch * 8]) = rb1;
    };

    gload(0);
    sstore(0);
    __syncthreads();

    for (int t = 0; t < nt; t++) {
        int p = t & 1;
        if (t + 1 < nt) gload(t + 1);

        uint32_t aoff = aBase + (uint32_t)p * (GBUF * 2);
        uint32_t boff = bBase + (uint32_t)p * (GBUF * 2);
#pragma unroll
        for (int ks = 0; ks < 2; ks++) {
            uint32_t af[4][4];
#pragma unroll
            for (int mt = 0; mt < 4; mt++)
                ldsm4(af[mt], aoff + ((wm + mt * 16 + lr) * GLDS + ks * 16 + lh * 8) * 2);
            uint32_t bf[2][4];
#pragma unroll
            for (int bt = 0; bt < 2; bt++)
                ldsm4(bf[bt], boff + ((wn + bt * 16 + lr) * GLDS + ks * 16 + lh * 8) * 2);
#pragma unroll
            for (int mt = 0; mt < 4; mt++) {
#pragma unroll
                for (int ntile = 0; ntile < 4; ntile++) {
                    int bt = ntile >> 1, sub = ntile & 1;
                    mma16816(acc[mt][ntile], af[mt], bf[bt][sub], bf[bt][sub + 2]);
                }
            }
        }
        __syncthreads();
        if (t + 1 < nt) {
            sstore((t + 1) & 1);
            __syncthreads();
        }
    }

    // epilogue: d0,d1 -> (m, n),(m, n+1); d2,d3 -> (m+8, n),(m+8, n+1)
    const int em = lane >> 2;
    const int en = (lane & 3) * 2;
#pragma unroll
    for (int mt = 0; mt < 4; mt++) {
#pragma unroll
        for (int ntile = 0; ntile < 4; ntile++) {
            int n = bn0 + wn + ntile * 8 + en;
            if (n >= Nreal) continue;
            int m = bm0 + wm + mt * 16 + em;
            float2 v0 = make_float2(acc[mt][ntile][0], acc[mt][ntile][1]);
            float2 v1 = make_float2(acc[mt][ntile][2], acc[mt][ntile][3]);
            if (bias) {
                float b0v = bias[n], b1v = bias[n + 1];
                v0.x += b0v; v0.y += b1v; v1.x += b0v; v1.y += b1v;
            }
            if (act == 1) {
                v0.x = softplusf(v0.x); v0.y = softplusf(v0.y);
                v1.x = softplusf(v1.x); v1.y = softplusf(v1.y);
            }
            *(float2*)(C + (size_t)m * ldc + n) = v0;
            *(float2*)(C + (size_t)(m + 8) * ldc + n) = v1;
        }
    }
}

// =============== causal depthwise conv + silu + bf16 triple ==============
__global__ void conv_silu_kernel(const float* __restrict__ xz,
                                 const float* __restrict__ cw, const float* __restrict__ cb,
                                 const float* __restrict__ cwb, const float* __restrict__ cbb,
                                 float* __restrict__ xcf, float* __restrict__ xcbk,
                                 __nv_bfloat16* __restrict__ xc3f,
                                 __nv_bfloat16* __restrict__ xc3b)
{
    int idx = blockIdx.x * blockDim.x + threadIdx.x;
    if (idx >= TT * DI) return;
    int d = idx % DI;
    int t = (idx / DI) % LL;
    int b = idx / (DI * LL);
    const float* xb = xz + (size_t)b * LL * NXZ + d;     // xs part, ld = 3072

    float accf = cb[d];
    if (t >= 3) accf = fmaf(xb[(size_t)(t - 3) * NXZ], cw[d * 4 + 0], accf);
    if (t >= 2) accf = fmaf(xb[(size_t)(t - 2) * NXZ], cw[d * 4 + 1], accf);
    if (t >= 1) accf = fmaf(xb[(size_t)(t - 1) * NXZ], cw[d * 4 + 2], accf);
    accf = fmaf(xb[(size_t)t * NXZ], cw[d * 4 + 3], accf);
    float vf = siluf(accf);

    int base = (LL - 1) - t;
    float accb = cbb[d];
    if (t >= 3) accb = fmaf(xb[(size_t)(base + 3) * NXZ], cwb[d * 4 + 0], accb);
    if (t >= 2) accb = fmaf(xb[(size_t)(base + 2) * NXZ], cwb[d * 4 + 1], accb);
    if (t >= 1) accb = fmaf(xb[(size_t)(base + 1) * NXZ], cwb[d * 4 + 2], accb);
    accb = fmaf(xb[(size_t)base * NXZ], cwb[d * 4 + 3], accb);
    float vb = siluf(accb);

    size_t r = (size_t)(b * LL + t);
    xcf[r * DI + d] = vf;
    xcbk[r * DI + d] = vb;
    __nv_bfloat16 hi, lo;
    split3(vf, hi, lo);
    __nv_bfloat16* d3 = xc3f + r * K3_BIG;
    d3[d] = hi; d3[DI + d] = lo; d3[2 * DI + d] = hi;
    split3(vb, hi, lo);
    d3 = xc3b + r * K3_BIG;
    d3[d] = hi; d3[DI + d] = lo; d3[2 * DI + d] = hi;
}

// ======================= selective scan ==================================
__global__ __launch_bounds__(256)
void scan_kernel(const float* __restrict__ xc0, const float* __restrict__ xc1,
                 const float* __restrict__ dl0, const float* __restrict__ dl1,
                 const float* __restrict__ pj0, const float* __restrict__ pj1,
                 const float* __restrict__ Alog0, const float* __restrict__ Alog1,
                 const float* __restrict__ Dp0, const float* __restrict__ Dp1,
                 float* __restrict__ y0, float* __restrict__ y1)
{
    int bid = blockIdx.x;
    int dgroup = bid % 96;
    int b = (bid / 96) % BB;
    int dir = bid / (96 * BB);

    const float* xc = dir ? xc1 : xc0;
    const float* dl = dir ? dl1 : dl0;
    const float* pj = dir ? pj1 : pj0;
    const float* Alog = dir ? Alog1 : Alog0;
    const float* Dp = dir ? Dp1 : Dp0;
    float* y = dir ? y1 : y0;

    int lane = threadIdx.x & 31;
    int w = threadIdx.x >> 5;
    int n = lane & 15;
    int d = dgroup * 16 + w * 2 + (lane >> 4);

    const float* xcp = xc + (size_t)b * LL * DI + d;
    const float* dlp = dl + (size_t)b * LL * DI + d;
    const float* pjB = pj + (size_t)b * LL * NPROJ + 48 + n;
    const float* pjC = pj + (size_t)b * LL * NPROJ + 64 + n;
    float* yp = y + (size_t)b * LL * DI + d;

    const float A = -__expf(Alog[d * DS + n]);
    const float Dd = Dp[d];

    float h = 0.0f;
    float dv = dlp[0], xv = xcp[0], Bv = pjB[0], Cv = pjC[0];

    for (int t = 0; t < LL; ++t) {
        float dv2 = 0.f, xv2 = 0.f, Bv2 = 0.f, Cv2 = 0.f;
        if (t + 1 < LL) {
            dv2 = dlp[(size_t)(t + 1) * DI];
            xv2 = xcp[(size_t)(t + 1) * DI];
            Bv2 = pjB[(size_t)(t + 1) * NPROJ];
            Cv2 = pjC[(size_t)(t + 1) * NPROJ];
        }
        float dA = __expf(dv * A);
        h = fmaf(dA, h, dv * xv * Bv);
        float p = h * Cv;
        p += __shfl_xor_sync(0xffffffffu, p, 1);
        p += __shfl_xor_sync(0xffffffffu, p, 2);
        p += __shfl_xor_sync(0xffffffffu, p, 4);
        p += __shfl_xor_sync(0xffffffffu, p, 8);
        if (n == 0) yp[(size_t)t * DI] = fmaf(Dd, xv, p);
        dv = dv2; xv = xv2; Bv = Bv2; Cv = Cv2;
    }
}

// ========== combine: 0.5*silu(z)*(y_f + rev(y_b)) -> bf16 triple ==========
__global__ void combine_kernel(const float* __restrict__ xz,
                               const float* __restrict__ yf,
                               const float* __restrict__ yb,
                               __nv_bfloat16* __restrict__ yc3)
{
    int idx = blockIdx.x * blockDim.x + threadIdx.x;
    if (idx >= TT * DI) return;
    int d = idx % DI;
    int l = (idx / DI) % LL;
    int b = idx / (DI * LL);
    float zz = xz[((size_t)b * LL + l) * NXZ + DI + d];
    float s = zz / (1.0f + __expf(-zz));
    float v = yf[idx] + yb[((size_t)b * LL + (LL - 1 - l)) * DI + d];
    v *= 0.5f * s;
    __nv_bfloat16 hi, lo; split3(v, hi, lo);
    __nv_bfloat16* d3 = yc3 + (size_t)(b * LL + l) * K3_BIG;
    d3[d] = hi; d3[DI + d] = lo; d3[2 * DI + d] = hi;
}

// ======================= launch ==========================================
extern "C" void kernel_launch(void* const* d_in, const int* in_sizes, int n_in,
                              void* d_out, int out_size)
{
    const float* x        = (const float*)d_in[0];
    const float* W_in_s   = (const float*)d_in[1];
    const float* W_in_g   = (const float*)d_in[2];
    const float* conv_w   = (const float*)d_in[3];
    const float* conv_b   = (const float*)d_in[4];
    const float* conv_w_b = (const float*)d_in[5];
    const float* conv_b_b = (const float*)d_in[6];
    const float* W_dt     = (const float*)d_in[7];
    const float* W_B      = (const float*)d_in[8];
    const float* W_C      = (const float*)d_in[9];
    const float* dtW      = (const float*)d_in[10];
    const float* dtb      = (const float*)d_in[11];
    const float* A_log    = (const float*)d_in[12];
    const float* Dp       = (const float*)d_in[13];
    const float* W_dt_b   = (const float*)d_in[14];
    const float* W_B_b    = (const float*)d_in[15];
    const float* W_C_b    = (const float*)d_in[16];
    const float* dtW_b    = (const float*)d_in[17];
    const float* dtb_b    = (const float*)d_in[18];
    const float* A_log_b  = (const float*)d_in[19];
    const float* Dp_b     = (const float*)d_in[20];
    const float* W_out    = (const float*)d_in[21];
    float* out = (float*)d_out;

    float *p_xz, *p_xc, *p_wp, *p_pj, *p_dl, *p_y;
    __nv_bfloat16 *p_x3, *p_Wcat3, *p_xc3, *p_wp3, *p_pj3, *p_dtW3, *p_yc3, *p_Wout3;
    cudaGetSymbolAddress((void**)&p_xz, g_xz);
    cudaGetSymbolAddress((void**)&p_x3, g_x3);
    cudaGetSymbolAddress((void**)&p_Wcat3, g_Wcat3);
    cudaGetSymbolAddress((void**)&p_xc, g_xc);
    cudaGetSymbolAddress((void**)&p_xc3, g_xc3);
    cudaGetSymbolAddress((void**)&p_wp, g_wproj);
    cudaGetSymbolAddress((void**)&p_wp3, g_wproj3);
    cudaGetSymbolAddress((void**)&p_pj, g_pj);
    cudaGetSymbolAddress((void**)&p_pj3, g_pj3);
    cudaGetSymbolAddress((void**)&p_dtW3, g_dtW3);
    cudaGetSymbolAddress((void**)&p_dl, g_delta);
    cudaGetSymbolAddress((void**)&p_y, g_y);
    cudaGetSymbolAddress((void**)&p_yc3, g_yc3);
    cudaGetSymbolAddress((void**)&p_Wout3, g_Wout3);

    float* xc0 = p_xc;  float* xc1 = p_xc + (size_t)TT * DI;
    float* pj0 = p_pj;  float* pj1 = p_pj + (size_t)TT * NPROJ;
    float* dl0 = p_dl;  float* dl1 = p_dl + (size_t)TT * DI;
    float* y0  = p_y;   float* y1  = p_y + (size_t)TT * DI;
    float* wp0 = p_wp;  float* wp1 = p_wp + (size_t)NPROJ * DI;
    __nv_bfloat16* xc3f = p_xc3;
    __nv_bfloat16* xc3b = p_xc3 + (size_t)TT * K3_BIG;
    __nv_bfloat16* wp3f = p_wp3;
    __nv_bfloat16* wp3b = p_wp3 + (size_t)NPROJ * K3_BIG;
    __nv_bfloat16* pj3f = p_pj3;
    __nv_bfloat16* pj3b = p_pj3 + (size_t)TT * K3_DT;
    __nv_bfloat16* dtW3f = p_dtW3;
    __nv_bfloat16* dtW3b = p_dtW3 + (size_t)DI * K3_DT;

    const int EW = 256;
    const int nEW = (TT * DI + EW - 1) / EW;
    auto cgrid = [](int total) { return (total + 255) / 256; };

    // weight prep
    concat_wproj<<<cgrid(NPROJ * DI), 256>>>(W_dt, W_B, W_C, W_dt_b, W_B_b, W_C_b, wp0, wp1);
    conv3_kernel<<<cgrid(TT * DM), 256>>>(x, DM, DM, DM, p_x3, 1, TT * DM);
    conv3_kernel<<<cgrid(DI * DM), 256>>>(W_in_s, DM, DM, DM, p_Wcat3, 0, DI * DM);
    conv3_kernel<<<cgrid(DI * DM), 256>>>(W_in_g, DM, DM, DM,
                                          p_Wcat3 + (size_t)DI * K3_IN, 0, DI * DM);
    conv3_kernel<<<cgrid(NPROJ * DI), 256>>>(wp0, DI, DI, DI, wp3f, 0, NPROJ * DI);
    conv3_kernel<<<cgrid(NPROJ * DI), 256>>>(wp1, DI, DI, DI, wp3b, 0, NPROJ * DI);
    conv3_kernel<<<cgrid(DI * 64), 256>>>(dtW, DR, DR, 64, dtW3f, 0, DI * 64);
    conv3_kernel<<<cgrid(DI * 64), 256>>>(dtW_b, DR, DR, 64, dtW3b, 0, DI * 64);
    conv3_kernel<<<cgrid(DM * DI), 256>>>(W_out, DI, DI, DI, p_Wout3, 0, DM * DI);

    // in-proj: xz[T,3072] = x3 @ Wcat3^T
    gemm_mma<<<dim3(NXZ / 128, TT / 128, 1), 256>>>(
        p_x3, p_x3, p_Wcat3, p_Wcat3, p_xz, p_xz, NXZ, K3_IN, NXZ,
        nullptr, nullptr, 0);

    // conv + silu + bf16 triple
    conv_silu_kernel<<<nEW, EW>>>(p_xz, conv_w, conv_b, conv_w_b, conv_b_b,
                                  xc0, xc1, xc3f, xc3b);

    // proj: pj[T,80] = xc3 @ wproj3^T (both dirs)
    gemm_mma<<<dim3(1, TT / 128, 2), 256>>>(
        xc3f, xc3b, wp3f, wp3b, pj0, pj1, NPROJ, K3_BIG, NPROJ,
        nullptr, nullptr, 0);

    // pj3 (dt_low bf16 triple, K padded 48->64)
    conv3_kernel<<<cgrid(TT * 64), 256>>>(pj0, NPROJ, DR, 64, pj3f, 1, TT * 64);
    conv3_kernel<<<cgrid(TT * 64), 256>>>(pj1, NPROJ, DR, 64, pj3b, 1, TT * 64);

    // delta = softplus(pj3 @ dtW3^T + dtb) (both dirs)
    gemm_mma<<<dim3(DI / 128, TT / 128, 2), 256>>>(
        pj3f, pj3b, dtW3f, dtW3b, dl0, dl1, DI, K3_DT, DI,
        dtb, dtb_b, 1);

    // selective scan
    scan_kernel<<<2 * BB * (DI / 16), 256>>>(
        xc0, xc1, dl0, dl1, pj0, pj1, A_log, A_log_b, Dp, Dp_b, y0, y1);

    // combine -> yc3 (bf16 triple)
    combine_kernel<<<nEW, EW>>>(p_xz, y0, y1, p_yc3);

    // out-proj: out[T,768] = yc3 @ Wout3^T
    gemm_mma<<<dim3(DM / 128, TT / 128, 1), 256>>>(
        p_yc3, p_yc3, p_Wout3, p_Wout3, out, out, DM, K3_BIG, DM,
        nullptr, nullptr, 0);
}

// round 4
// speedup vs baseline: 1.1429x; 1.0188x over previous
#include <cuda_runtime.h>
#include <cuda_bf16.h>
#include <cstdint>
#include <cstddef>

#define DM 768
#define DI 1536
#define DS 16
#define DR 48
#define BB 2
#define LL 1024
#define TT (BB*LL)
#define NPROJ 80
#define NXZ 3072          // xs(1536) + z(1536) fused in-proj
#define K3_IN  2304       // 3*768
#define K3_BIG 4608       // 3*1536
#define K3_DT  192        // 3*64 (48 padded to 64)

// ======================= scratch (device globals) =======================
__device__ __align__(128) float g_xz[TT*NXZ];
__device__ __align__(128) __nv_bfloat16 g_x3[(size_t)TT*K3_IN];
__device__ __align__(128) __nv_bfloat16 g_Wcat3[(size_t)NXZ*K3_IN];
__device__ __align__(128) float g_xc[2][TT*DI];
__device__ __align__(128) __nv_bfloat16 g_xc3[2][(size_t)TT*K3_BIG];
__device__ __align__(128) float g_wproj[2][NPROJ*DI];
__device__ __align__(128) __nv_bfloat16 g_wproj3[2][(size_t)NPROJ*K3_BIG];
__device__ __align__(128) float g_pj[2][TT*NPROJ];
__device__ __align__(128) __nv_bfloat16 g_pj3[2][(size_t)TT*K3_DT];
__device__ __align__(128) __nv_bfloat16 g_dtW3[2][(size_t)DI*K3_DT];
__device__ __align__(128) float g_delta[2][TT*DI];
__device__ __align__(128) float g_y[2][TT*DI];
__device__ __align__(128) __nv_bfloat16 g_yc3[(size_t)TT*K3_BIG];
__device__ __align__(128) __nv_bfloat16 g_Wout3[(size_t)DM*K3_BIG];

__device__ __forceinline__ float siluf(float x) { return x / (1.0f + __expf(-x)); }
__device__ __forceinline__ float softplusf(float x) {
    return (x > 20.0f) ? x : log1pf(__expf(x));
}
__device__ __forceinline__ void split3(float v, __nv_bfloat16& hi, __nv_bfloat16& lo) {
    hi = __float2bfloat16(v);
    lo = __float2bfloat16(v - __bfloat162float(hi));
}

// =============== bf16-triple conversion: fp32[rows,K] -> bf16[rows,3*Kseg]
// isA: segs {hi, lo, hi};  !isA (B-side): segs {hi, hi, lo}
__global__ void conv3_kernel(const float* __restrict__ src, int lds, int Kreal,
                             int Kseg, __nv_bfloat16* __restrict__ dst, int isA,
                             int total)
{
    int idx = blockIdx.x * blockDim.x + threadIdx.x;
    if (idx >= total) return;
    int r = idx / Kseg, k = idx - r * Kseg;
    float v = (k < Kreal) ? src[(size_t)r * lds + k] : 0.0f;
    __nv_bfloat16 hi, lo; split3(v, hi, lo);
    size_t base = (size_t)r * 3 * Kseg;
    if (isA) { dst[base + k] = hi; dst[base + Kseg + k] = lo; dst[base + 2*Kseg + k] = hi; }
    else     { dst[base + k] = hi; dst[base + Kseg + k] = hi; dst[base + 2*Kseg + k] = lo; }
}

// =============== concat dt/B/C weights into [80,1536] per dir =============
__global__ void concat_wproj(const float* __restrict__ Wdt, const float* __restrict__ WB,
                             const float* __restrict__ WC,
                             const float* __restrict__ Wdtb, const float* __restrict__ WBb,
                             const float* __restrict__ WCb,
                             float* __restrict__ w0, float* __restrict__ w1)
{
    int i = blockIdx.x * blockDim.x + threadIdx.x;
    if (i >= NPROJ * DI) return;
    int r = i / DI, c = i % DI;
    float vf, vb;
    if (r < 48)      { vf = Wdt[r * DI + c];        vb = Wdtb[r * DI + c]; }
    else if (r < 64) { vf = WB[(r - 48) * DI + c];  vb = WBb[(r - 48) * DI + c]; }
    else             { vf = WC[(r - 64) * DI + c];  vb = WCb[(r - 64) * DI + c]; }
    w0[i] = vf; w1[i] = vb;
}

// ======================= mma.sync bf16 NT GEMM (cp.async 4-stage) =========
// C[z][2048, Nreal] = A3[z][2048, K3] * B3[z][Npad, K3]^T  (bf16 in, fp32 acc)
// 128x128x32 tile, 8 warps (2x4), 64x32 per warp, m16n8k16 HMMA.
#define GBK 32
#define GLDS 40                  // padded row stride (bf16): 32 + 8
#define STAGE_HALF (128*GLDS*2)  // bytes per A (or B) stage = 10240
#define STAGE_B (2*STAGE_HALF)   // bytes per stage (A+B) = 20480
#define NSTAGE 4
#define GSMEM (NSTAGE*STAGE_B)   // 81920

__device__ __forceinline__ void ldsm4(uint32_t* r, uint32_t addr) {
    asm volatile("ldmatrix.sync.aligned.m8n8.x4.shared.b16 {%0,%1,%2,%3}, [%4];"
                 : "=r"(r[0]), "=r"(r[1]), "=r"(r[2]), "=r"(r[3]) : "r"(addr));
}
__device__ __forceinline__ void mma16816(float* d, const uint32_t* a,
                                         uint32_t b0, uint32_t b1) {
    asm volatile("mma.sync.aligned.m16n8k16.row.col.f32.bf16.bf16.f32 "
                 "{%0,%1,%2,%3}, {%4,%5,%6,%7}, {%8,%9}, {%0,%1,%2,%3};"
                 : "+f"(d[0]), "+f"(d[1]), "+f"(d[2]), "+f"(d[3])
                 : "r"(a[0]), "r"(a[1]), "r"(a[2]), "r"(a[3]), "r"(b0), "r"(b1));
}
__device__ __forceinline__ void cpa16(uint32_t dst, const void* src, int sz) {
    asm volatile("cp.async.cg.shared.global [%0], [%1], 16, %2;"
                 :: "r"(dst), "l"(src), "r"(sz) : "memory");
}
__device__ __forceinline__ void cpa_commit() {
    asm volatile("cp.async.commit_group;" ::: "memory");
}
__device__ __forceinline__ void cpa_wait2() {
    asm volatile("cp.async.wait_group 2;" ::: "memory");
}

__global__ __launch_bounds__(256, 2)
void gemm_mma(const __nv_bfloat16* __restrict__ A0, const __nv_bfloat16* __restrict__ A1,
              const __nv_bfloat16* __restrict__ B0, const __nv_bfloat16* __restrict__ B1,
              float* __restrict__ C0, float* __restrict__ C1,
              int ldc, int K3, int Nreal,
              const float* __restrict__ bias0, const float* __restrict__ bias1, int act)
{
    extern __shared__ char smem[];

    const int z = blockIdx.z;
    const __nv_bfloat16* A = z ? A1 : A0;
    const __nv_bfloat16* B = z ? B1 : B0;
    float* C = z ? C1 : C0;
    const float* bias = z ? bias1 : bias0;

    const int tid = threadIdx.x;
    const int lane = tid & 31;
    const int wid = tid >> 5;
    const int bm0 = blockIdx.y * 128;
    const int bn0 = blockIdx.x * 128;
    const int wm = (wid >> 2) * 64;     // 0 or 64
    const int wn = (wid & 3) * 32;      // 0,32,64,96

    const uint32_t sBase = (uint32_t)__cvta_generic_to_shared(smem);
    const int lr = lane & 15, lh = lane >> 4;

    float acc[4][4][4];
#pragma unroll
    for (int i = 0; i < 4; i++)
#pragma unroll
        for (int j = 0; j < 4; j++)
#pragma unroll
            for (int v = 0; v < 4; v++) acc[i][j][v] = 0.0f;

    const int nt = K3 / GBK;
    // load indexing: 512 16B-chunks per half-stage, 2 per thread
    const int row0 = tid >> 1;              // rows 0..127, 2 chunks/row half
    const int ch0 = (tid & 1) << 1;         // chunk 0/2 -> this thread does ch,ch+1

    auto load_stage = [&](int s, int t) {
        uint32_t sb = sBase + (uint32_t)s * STAGE_B;
        size_t koff = (size_t)t * GBK;
        const __nv_bfloat16* Ap = A + (size_t)(bm0 + row0) * K3 + koff;
        int brow = bn0 + row0;
        int bsz = (brow < Nreal) ? 16 : 0;
        const __nv_bfloat16* Bp = B + (size_t)((brow < Nreal) ? brow : 0) * K3 + koff;
#pragma unroll
        for (int c = 0; c < 2; c++) {
            int ch = ch0 + c;
            uint32_t soff = (uint32_t)(row0 * 80 + ch * 16);
            cpa16(sb + soff, Ap + ch * 8, 16);
            cpa16(sb + STAGE_HALF + soff, Bp + ch * 8, bsz);
        }
    };

#pragma unroll
    for (int s = 0; s < NSTAGE - 1; s++) {
        if (s < nt) load_stage(s, s);
        cpa_commit();
    }

    for (int t = 0; t < nt; t++) {
        cpa_wait2();
        __syncthreads();

        int tn = t + NSTAGE - 1;
        if (tn < nt) load_stage(tn & (NSTAGE - 1), tn);
        cpa_commit();

        uint32_t aoff = sBase + (uint32_t)(t & (NSTAGE - 1)) * STAGE_B;
        uint32_t boff = aoff + STAGE_HALF;
#pragma unroll
        for (int ks = 0; ks < 2; ks++) {
            uint32_t af[4][4];
#pragma unroll
            for (int mt = 0; mt < 4; mt++)
                ldsm4(af[mt], aoff + ((wm + mt * 16 + lr) * GLDS + ks * 16 + lh * 8) * 2);
            uint32_t bf[2][4];
#pragma unroll
            for (int bt = 0; bt < 2; bt++)
                ldsm4(bf[bt], boff + ((wn + bt * 16 + lr) * GLDS + ks * 16 + lh * 8) * 2);
#pragma unroll
            for (int mt = 0; mt < 4; mt++) {
#pragma unroll
                for (int ntile = 0; ntile < 4; ntile++) {
                    int bt = ntile >> 1, sub = ntile & 1;
                    mma16816(acc[mt][ntile], af[mt], bf[bt][sub], bf[bt][sub + 2]);
                }
            }
        }
    }

    // epilogue: d0,d1 -> (m, n),(m, n+1); d2,d3 -> (m+8, n),(m+8, n+1)
    const int em = lane >> 2;
    const int en = (lane & 3) * 2;
#pragma unroll
    for (int mt = 0; mt < 4; mt++) {
#pragma unroll
        for (int ntile = 0; ntile < 4; ntile++) {
            int n = bn0 + wn + ntile * 8 + en;
            if (n >= Nreal) continue;
            int m = bm0 + wm + mt * 16 + em;
            float2 v0 = make_float2(acc[mt][ntile][0], acc[mt][ntile][1]);
            float2 v1 = make_float2(acc[mt][ntile][2], acc[mt][ntile][3]);
            if (bias) {
                float b0v = bias[n], b1v = bias[n + 1];
                v0.x += b0v; v0.y += b1v; v1.x += b0v; v1.y += b1v;
            }
            if (act == 1) {
                v0.x = softplusf(v0.x); v0.y = softplusf(v0.y);
                v1.x = softplusf(v1.x); v1.y = softplusf(v1.y);
            }
            *(float2*)(C + (size_t)m * ldc + n) = v0;
            *(float2*)(C + (size_t)(m + 8) * ldc + n) = v1;
        }
    }
}

// =============== causal depthwise conv + silu + bf16 triple ==============
__global__ void conv_silu_kernel(const float* __restrict__ xz,
                                 const float* __restrict__ cw, const float* __restrict__ cb,
                                 const float* __restrict__ cwb, const float* __restrict__ cbb,
                                 float* __restrict__ xcf, float* __restrict__ xcbk,
                                 __nv_bfloat16* __restrict__ xc3f,
                                 __nv_bfloat16* __restrict__ xc3b)
{
    int idx = blockIdx.x * blockDim.x + threadIdx.x;
    if (idx >= TT * DI) return;
    int d = idx % DI;
    int t = (idx / DI) % LL;
    int b = idx / (DI * LL);
    const float* xb = xz + (size_t)b * LL * NXZ + d;     // xs part, ld = 3072

    float accf = cb[d];
    if (t >= 3) accf = fmaf(xb[(size_t)(t - 3) * NXZ], cw[d * 4 + 0], accf);
    if (t >= 2) accf = fmaf(xb[(size_t)(t - 2) * NXZ], cw[d * 4 + 1], accf);
    if (t >= 1) accf = fmaf(xb[(size_t)(t - 1) * NXZ], cw[d * 4 + 2], accf);
    accf = fmaf(xb[(size_t)t * NXZ], cw[d * 4 + 3], accf);
    float vf = siluf(accf);

    int base = (LL - 1) - t;
    float accb = cbb[d];
    if (t >= 3) accb = fmaf(xb[(size_t)(base + 3) * NXZ], cwb[d * 4 + 0], accb);
    if (t >= 2) accb = fmaf(xb[(size_t)(base + 2) * NXZ], cwb[d * 4 + 1], accb);
    if (t >= 1) accb = fmaf(xb[(size_t)(base + 1) * NXZ], cwb[d * 4 + 2], accb);
    accb = fmaf(xb[(size_t)base * NXZ], cwb[d * 4 + 3], accb);
    float vb = siluf(accb);

    size_t r = (size_t)(b * LL + t);
    xcf[r * DI + d] = vf;
    xcbk[r * DI + d] = vb;
    __nv_bfloat16 hi, lo;
    split3(vf, hi, lo);
    __nv_bfloat16* d3 = xc3f + r * K3_BIG;
    d3[d] = hi; d3[DI + d] = lo; d3[2 * DI + d] = hi;
    split3(vb, hi, lo);
    d3 = xc3b + r * K3_BIG;
    d3[d] = hi; d3[DI + d] = lo; d3[2 * DI + d] = hi;
}

// ======================= selective scan ==================================
__global__ __launch_bounds__(256)
void scan_kernel(const float* __restrict__ xc0, const float* __restrict__ xc1,
                 const float* __restrict__ dl0, const float* __restrict__ dl1,
                 const float* __restrict__ pj0, const float* __restrict__ pj1,
                 const float* __restrict__ Alog0, const float* __restrict__ Alog1,
                 const float* __restrict__ Dp0, const float* __restrict__ Dp1,
                 float* __restrict__ y0, float* __restrict__ y1)
{
    int bid = blockIdx.x;
    int dgroup = bid % 96;
    int b = (bid / 96) % BB;
    int dir = bid / (96 * BB);

    const float* xc = dir ? xc1 : xc0;
    const float* dl = dir ? dl1 : dl0;
    const float* pj = dir ? pj1 : pj0;
    const float* Alog = dir ? Alog1 : Alog0;
    const float* Dp = dir ? Dp1 : Dp0;
    float* y = dir ? y1 : y0;

    int lane = threadIdx.x & 31;
    int w = threadIdx.x >> 5;
    int n = lane & 15;
    int d = dgroup * 16 + w * 2 + (lane >> 4);

    const float* xcp = xc + (size_t)b * LL * DI + d;
    const float* dlp = dl + (size_t)b * LL * DI + d;
    const float* pjB = pj + (size_t)b * LL * NPROJ + 48 + n;
    const float* pjC = pj + (size_t)b * LL * NPROJ + 64 + n;
    float* yp = y + (size_t)b * LL * DI + d;

    const float A = -__expf(Alog[d * DS + n]);
    const float Dd = Dp[d];

    float h = 0.0f;
    float dv = dlp[0], xv = xcp[0], Bv = pjB[0], Cv = pjC[0];

    for (int t = 0; t < LL; ++t) {
        float dv2 = 0.f, xv2 = 0.f, Bv2 = 0.f, Cv2 = 0.f;
        if (t + 1 < LL) {
            dv2 = dlp[(size_t)(t + 1) * DI];
            xv2 = xcp[(size_t)(t + 1) * DI];
            Bv2 = pjB[(size_t)(t + 1) * NPROJ];
            Cv2 = pjC[(size_t)(t + 1) * NPROJ];
        }
        float dA = __expf(dv * A);
        h = fmaf(dA, h, dv * xv * Bv);
        float p = h * Cv;
        p += __shfl_xor_sync(0xffffffffu, p, 1);
        p += __shfl_xor_sync(0xffffffffu, p, 2);
        p += __shfl_xor_sync(0xffffffffu, p, 4);
        p += __shfl_xor_sync(0xffffffffu, p, 8);
        if (n == 0) yp[(size_t)t * DI] = fmaf(Dd, xv, p);
        dv = dv2; xv = xv2; Bv = Bv2; Cv = Cv2;
    }
}

// ========== combine: 0.5*silu(z)*(y_f + rev(y_b)) -> bf16 triple ==========
__global__ void combine_kernel(const float* __restrict__ xz,
                               const float* __restrict__ yf,
                               const float* __restrict__ yb,
                               __nv_bfloat16* __restrict__ yc3)
{
    int idx = blockIdx.x * blockDim.x + threadIdx.x;
    if (idx >= TT * DI) return;
    int d = idx % DI;
    int l = (idx / DI) % LL;
    int b = idx / (DI * LL);
    float zz = xz[((size_t)b * LL + l) * NXZ + DI + d];
    float s = zz / (1.0f + __expf(-zz));
    float v = yf[idx] + yb[((size_t)b * LL + (LL - 1 - l)) * DI + d];
    v *= 0.5f * s;
    __nv_bfloat16 hi, lo; split3(v, hi, lo);
    __nv_bfloat16* d3 = yc3 + (size_t)(b * LL + l) * K3_BIG;
    d3[d] = hi; d3[DI + d] = lo; d3[2 * DI + d] = hi;
}

// ======================= launch ==========================================
extern "C" void kernel_launch(void* const* d_in, const int* in_sizes, int n_in,
                              void* d_out, int out_size)
{
    const float* x        = (const float*)d_in[0];
    const float* W_in_s   = (const float*)d_in[1];
    const float* W_in_g   = (const float*)d_in[2];
    const float* conv_w   = (const float*)d_in[3];
    const float* conv_b   = (const float*)d_in[4];
    const float* conv_w_b = (const float*)d_in[5];
    const float* conv_b_b = (const float*)d_in[6];
    const float* W_dt     = (const float*)d_in[7];
    const float* W_B      = (const float*)d_in[8];
    const float* W_C      = (const float*)d_in[9];
    const float* dtW      = (const float*)d_in[10];
    const float* dtb      = (const float*)d_in[11];
    const float* A_log    = (const float*)d_in[12];
    const float* Dp       = (const float*)d_in[13];
    const float* W_dt_b   = (const float*)d_in[14];
    const float* W_B_b    = (const float*)d_in[15];
    const float* W_C_b    = (const float*)d_in[16];
    const float* dtW_b    = (const float*)d_in[17];
    const float* dtb_b    = (const float*)d_in[18];
    const float* A_log_b  = (const float*)d_in[19];
    const float* Dp_b     = (const float*)d_in[20];
    const float* W_out    = (const float*)d_in[21];
    float* out = (float*)d_out;

    cudaFuncSetAttribute(gemm_mma, cudaFuncAttributeMaxDynamicSharedMemorySize, GSMEM);

    float *p_xz, *p_xc, *p_wp, *p_pj, *p_dl, *p_y;
    __nv_bfloat16 *p_x3, *p_Wcat3, *p_xc3, *p_wp3, *p_pj3, *p_dtW3, *p_yc3, *p_Wout3;
    cudaGetSymbolAddress((void**)&p_xz, g_xz);
    cudaGetSymbolAddress((void**)&p_x3, g_x3);
    cudaGetSymbolAddress((void**)&p_Wcat3, g_Wcat3);
    cudaGetSymbolAddress((void**)&p_xc, g_xc);
    cudaGetSymbolAddress((void**)&p_xc3, g_xc3);
    cudaGetSymbolAddress((void**)&p_wp, g_wproj);
    cudaGetSymbolAddress((void**)&p_wp3, g_wproj3);
    cudaGetSymbolAddress((void**)&p_pj, g_pj);
    cudaGetSymbolAddress((void**)&p_pj3, g_pj3);
    cudaGetSymbolAddress((void**)&p_dtW3, g_dtW3);
    cudaGetSymbolAddress((void**)&p_dl, g_delta);
    cudaGetSymbolAddress((void**)&p_y, g_y);
    cudaGetSymbolAddress((void**)&p_yc3, g_yc3);
    cudaGetSymbolAddress((void**)&p_Wout3, g_Wout3);

    float* xc0 = p_xc;  float* xc1 = p_xc + (size_t)TT * DI;
    float* pj0 = p_pj;  float* pj1 = p_pj + (size_t)TT * NPROJ;
    float* dl0 = p_dl;  float* dl1 = p_dl + (size_t)TT * DI;
    float* y0  = p_y;   float* y1  = p_y + (size_t)TT * DI;
    float* wp0 = p_wp;  float* wp1 = p_wp + (size_t)NPROJ * DI;
    __nv_bfloat16* xc3f = p_xc3;
    __nv_bfloat16* xc3b = p_xc3 + (size_t)TT * K3_BIG;
    __nv_bfloat16* wp3f = p_wp3;
    __nv_bfloat16* wp3b = p_wp3 + (size_t)NPROJ * K3_BIG;
    __nv_bfloat16* pj3f = p_pj3;
    __nv_bfloat16* pj3b = p_pj3 + (size_t)TT * K3_DT;
    __nv_bfloat16* dtW3f = p_dtW3;
    __nv_bfloat16* dtW3b = p_dtW3 + (size_t)DI * K3_DT;

    const int EW = 256;
    const int nEW = (TT * DI + EW - 1) / EW;
    auto cgrid = [](int total) { return (total + 255) / 256; };

    // weight prep
    concat_wproj<<<cgrid(NPROJ * DI), 256>>>(W_dt, W_B, W_C, W_dt_b, W_B_b, W_C_b, wp0, wp1);
    conv3_kernel<<<cgrid(TT * DM), 256>>>(x, DM, DM, DM, p_x3, 1, TT * DM);
    conv3_kernel<<<cgrid(DI * DM), 256>>>(W_in_s, DM, DM, DM, p_Wcat3, 0, DI * DM);
    conv3_kernel<<<cgrid(DI * DM), 256>>>(W_in_g, DM, DM, DM,
                                          p_Wcat3 + (size_t)DI * K3_IN, 0, DI * DM);
    conv3_kernel<<<cgrid(NPROJ * DI), 256>>>(wp0, DI, DI, DI, wp3f, 0, NPROJ * DI);
    conv3_kernel<<<cgrid(NPROJ * DI), 256>>>(wp1, DI, DI, DI, wp3b, 0, NPROJ * DI);
    conv3_kernel<<<cgrid(DI * 64), 256>>>(dtW, DR, DR, 64, dtW3f, 0, DI * 64);
    conv3_kernel<<<cgrid(DI * 64), 256>>>(dtW_b, DR, DR, 64, dtW3b, 0, DI * 64);
    conv3_kernel<<<cgrid(DM * DI), 256>>>(W_out, DI, DI, DI, p_Wout3, 0, DM * DI);

    // in-proj: xz[T,3072] = x3 @ Wcat3^T
    gemm_mma<<<dim3(NXZ / 128, TT / 128, 1), 256, GSMEM>>>(
        p_x3, p_x3, p_Wcat3, p_Wcat3, p_xz, p_xz, NXZ, K3_IN, NXZ,
        nullptr, nullptr, 0);

    // conv + silu + bf16 triple
    conv_silu_kernel<<<nEW, EW>>>(p_xz, conv_w, conv_b, conv_w_b, conv_b_b,
                                  xc0, xc1, xc3f, xc3b);

    // proj: pj[T,80] = xc3 @ wproj3^T (both dirs)
    gemm_mma<<<dim3(1, TT / 128, 2), 256, GSMEM>>>(
        xc3f, xc3b, wp3f, wp3b, pj0, pj1, NPROJ, K3_BIG, NPROJ,
        nullptr, nullptr, 0);

    // pj3 (dt_low bf16 triple, K padded 48->64)
    conv3_kernel<<<cgrid(TT * 64), 256>>>(pj0, NPROJ, DR, 64, pj3f, 1, TT * 64);
    conv3_kernel<<<cgrid(TT * 64), 256>>>(pj1, NPROJ, DR, 64, pj3b, 1, TT * 64);

    // delta = softplus(pj3 @ dtW3^T + dtb) (both dirs)
    gemm_mma<<<dim3(DI / 128, TT / 128, 2), 256, GSMEM>>>(
        pj3f, pj3b, dtW3f, dtW3b, dl0, dl1, DI, K3_DT, DI,
        dtb, dtb_b, 1);

    // selective scan
    scan_kernel<<<2 * BB * (DI / 16), 256>>>(
        xc0, xc1, dl0, dl1, pj0, pj1, A_log, A_log_b, Dp, Dp_b, y0, y1);

    // combine -> yc3 (bf16 triple)
    combine_kernel<<<nEW, EW>>>(p_xz, y0, y1, p_yc3);

    // out-proj: out[T,768] = yc3 @ Wout3^T
    gemm_mma<<<dim3(DM / 128, TT / 128, 1), 256, GSMEM>>>(
        p_yc3, p_yc3, p_Wout3, p_Wout3, out, out, DM, K3_BIG, DM,
        nullptr, nullptr, 0);
}

// round 5
// speedup vs baseline: 1.2454x; 1.0897x over previous
#include <cuda_runtime.h>
#include <cuda_bf16.h>
#include <cstdint>
#include <cstddef>

#define DM 768
#define DI 1536
#define DS 16
#define DR 48
#define BB 2
#define LL 1024
#define TT (BB*LL)
#define NPROJ 80
#define NXZ 3072          // xs(1536) + z(1536) fused in-proj
#define K3_IN  2304       // 3*768
#define K3_BIG 4608       // 3*1536
#define K3_DT  192        // 3*64 (48 padded to 64)

// ======================= scratch (device globals) =======================
__device__ __align__(128) float g_xz[TT*NXZ];
__device__ __align__(128) __nv_bfloat16 g_x3[(size_t)TT*K3_IN];
__device__ __align__(128) __nv_bfloat16 g_Wcat3[(size_t)NXZ*K3_IN];
__device__ __align__(128) float g_xc[2][TT*DI];
__device__ __align__(128) __nv_bfloat16 g_xc3[2][(size_t)TT*K3_BIG];
__device__ __align__(128) float g_wproj[2][NPROJ*DI];
__device__ __align__(128) __nv_bfloat16 g_wproj3[2][(size_t)NPROJ*K3_BIG];
__device__ __align__(128) float g_pj[2][TT*NPROJ];
__device__ __align__(128) __nv_bfloat16 g_pj3[2][(size_t)TT*K3_DT];   // pad cols stay 0
__device__ __align__(128) __nv_bfloat16 g_dtW3[2][(size_t)DI*K3_DT];
__device__ __align__(128) float g_delta[2][TT*DI];
__device__ __align__(128) float g_y[2][TT*DI];
__device__ __align__(128) __nv_bfloat16 g_yc3[(size_t)TT*K3_BIG];
__device__ __align__(128) __nv_bfloat16 g_Wout3[(size_t)DM*K3_BIG];

__device__ __forceinline__ float siluf(float x) { return x / (1.0f + __expf(-x)); }
__device__ __forceinline__ float softplusf(float x) {
    return (x > 20.0f) ? x : log1pf(__expf(x));
}
__device__ __forceinline__ void split3(float v, __nv_bfloat16& hi, __nv_bfloat16& lo) {
    hi = __float2bfloat16(v);
    lo = __float2bfloat16(v - __bfloat162float(hi));
}

// =============== bf16-triple conversion: fp32[rows,K] -> bf16[rows,3*Kseg]
// isA: segs {hi, lo, hi};  !isA (B-side): segs {hi, hi, lo}
__global__ void conv3_kernel(const float* __restrict__ src, int lds, int Kreal,
                             int Kseg, __nv_bfloat16* __restrict__ dst, int isA,
                             int total)
{
    int idx = blockIdx.x * blockDim.x + threadIdx.x;
    if (idx >= total) return;
    int r = idx / Kseg, k = idx - r * Kseg;
    float v = (k < Kreal) ? src[(size_t)r * lds + k] : 0.0f;
    __nv_bfloat16 hi, lo; split3(v, hi, lo);
    size_t base = (size_t)r * 3 * Kseg;
    if (isA) { dst[base + k] = hi; dst[base + Kseg + k] = lo; dst[base + 2*Kseg + k] = hi; }
    else     { dst[base + k] = hi; dst[base + Kseg + k] = hi; dst[base + 2*Kseg + k] = lo; }
}

// =============== concat dt/B/C weights into [80,1536] per dir =============
__global__ void concat_wproj(const float* __restrict__ Wdt, const float* __restrict__ WB,
                             const float* __restrict__ WC,
                             const float* __restrict__ Wdtb, const float* __restrict__ WBb,
                             const float* __restrict__ WCb,
                             float* __restrict__ w0, float* __restrict__ w1)
{
    int i = blockIdx.x * blockDim.x + threadIdx.x;
    if (i >= NPROJ * DI) return;
    int r = i / DI, c = i % DI;
    float vf, vb;
    if (r < 48)      { vf = Wdt[r * DI + c];        vb = Wdtb[r * DI + c]; }
    else if (r < 64) { vf = WB[(r - 48) * DI + c];  vb = WBb[(r - 48) * DI + c]; }
    else             { vf = WC[(r - 64) * DI + c];  vb = WCb[(r - 64) * DI + c]; }
    w0[i] = vf; w1[i] = vb;
}

// =============== fused remaining weight conversions (B-side) ==============
// regions: wp3f, wp3b, dtW3f, dtW3b, Wout3
#define RW0 (NPROJ*DI)
#define RW1 (2*NPROJ*DI)
#define RW2 (2*NPROJ*DI + DI*64)
#define RW3 (2*NPROJ*DI + 2*DI*64)
#define RWT (2*NPROJ*DI + 2*DI*64 + DM*DI)
__global__ void prep_rest_kernel(const float* __restrict__ wp0, const float* __restrict__ wp1,
                                 const float* __restrict__ dtW, const float* __restrict__ dtWb,
                                 const float* __restrict__ Wout,
                                 __nv_bfloat16* __restrict__ wp3f, __nv_bfloat16* __restrict__ wp3b,
                                 __nv_bfloat16* __restrict__ dtW3f, __nv_bfloat16* __restrict__ dtW3b,
                                 __nv_bfloat16* __restrict__ Wout3)
{
    for (int idx = blockIdx.x * blockDim.x + threadIdx.x; idx < RWT;
         idx += gridDim.x * blockDim.x) {
        const float* src; __nv_bfloat16* dst; int lds, Kreal, Kseg, local;
        if (idx < RW0)      { local = idx;       src = wp0;  dst = wp3f;  lds = DI; Kreal = DI; Kseg = DI; }
        else if (idx < RW1) { local = idx - RW0; src = wp1;  dst = wp3b;  lds = DI; Kreal = DI; Kseg = DI; }
        else if (idx < RW2) { local = idx - RW1; src = dtW;  dst = dtW3f; lds = DR; Kreal = DR; Kseg = 64; }
        else if (idx < RW3) { local = idx - RW2; src = dtWb; dst = dtW3b; lds = DR; Kreal = DR; Kseg = 64; }
        else                { local = idx - RW3; src = Wout; dst = Wout3; lds = DI; Kreal = DI; Kseg = DI; }
        int r = local / Kseg, k = local - r * Kseg;
        float v = (k < Kreal) ? src[(size_t)r * lds + k] : 0.0f;
        __nv_bfloat16 hi, lo; split3(v, hi, lo);
        size_t base = (size_t)r * 3 * Kseg;
        dst[base + k] = hi; dst[base + Kseg + k] = hi; dst[base + 2*Kseg + k] = lo;
    }
}

// ======================= mma.sync bf16 NT GEMM (cp.async 4-stage) =========
// C[z][2048, Nreal] = A3[z][2048, K3] * B3[z][Npad, K3]^T  (bf16 in, fp32 acc)
// BM x 128 x 32 tile, 8 warps (2x4), (BM/2)x32 per warp, m16n8k16 HMMA.
#define GBK 32
#define GLDS 40                  // padded row stride (bf16): 32 + 8
#define NSTAGE 4

__device__ __forceinline__ void ldsm4(uint32_t* r, uint32_t addr) {
    asm volatile("ldmatrix.sync.aligned.m8n8.x4.shared.b16 {%0,%1,%2,%3}, [%4];"
                 : "=r"(r[0]), "=r"(r[1]), "=r"(r[2]), "=r"(r[3]) : "r"(addr));
}
__device__ __forceinline__ void mma16816(float* d, const uint32_t* a,
                                         uint32_t b0, uint32_t b1) {
    asm volatile("mma.sync.aligned.m16n8k16.row.col.f32.bf16.bf16.f32 "
                 "{%0,%1,%2,%3}, {%4,%5,%6,%7}, {%8,%9}, {%0,%1,%2,%3};"
                 : "+f"(d[0]), "+f"(d[1]), "+f"(d[2]), "+f"(d[3])
                 : "r"(a[0]), "r"(a[1]), "r"(a[2]), "r"(a[3]), "r"(b0), "r"(b1));
}
__device__ __forceinline__ void cpa16(uint32_t dst, const void* src, int sz) {
    asm volatile("cp.async.cg.shared.global [%0], [%1], 16, %2;"
                 :: "r"(dst), "l"(src), "r"(sz) : "memory");
}
__device__ __forceinline__ void cpa_commit() {
    asm volatile("cp.async.commit_group;" ::: "memory");
}
__device__ __forceinline__ void cpa_wait2() {
    asm volatile("cp.async.wait_group 2;" ::: "memory");
}

template<int BM>
__global__ __launch_bounds__(256, 2)
void gemm_mma(const __nv_bfloat16* __restrict__ A0, const __nv_bfloat16* __restrict__ A1,
              const __nv_bfloat16* __restrict__ B0, const __nv_bfloat16* __restrict__ B1,
              float* __restrict__ C0, float* __restrict__ C1,
              int ldc, int K3, int Nreal,
              const float* __restrict__ bias0, const float* __restrict__ bias1, int act,
              __nv_bfloat16* __restrict__ D30, __nv_bfloat16* __restrict__ D31)
{
    constexpr int A_HALF = BM * 80;            // bytes per A stage
    constexpr int STAGE_B = A_HALF + 128 * 80; // bytes per stage (A+B)
    constexpr int MT = BM / 32;                // m16 tiles per warp

    extern __shared__ char smem[];

    const int z = blockIdx.z;
    const __nv_bfloat16* A = z ? A1 : A0;
    const __nv_bfloat16* B = z ? B1 : B0;
    float* C = z ? C1 : C0;
    const float* bias = z ? bias1 : bias0;
    __nv_bfloat16* D3 = z ? D31 : D30;

    const int tid = threadIdx.x;
    const int lane = tid & 31;
    const int wid = tid >> 5;
    const int bm0 = blockIdx.y * BM;
    const int bn0 = blockIdx.x * 128;
    const int wm = (wid >> 2) * (BM / 2);
    const int wn = (wid & 3) * 32;

    const uint32_t sBase = (uint32_t)__cvta_generic_to_shared(smem);
    const int lr = lane & 15, lh = lane >> 4;

    float acc[MT][4][4];
#pragma unroll
    for (int i = 0; i < MT; i++)
#pragma unroll
        for (int j = 0; j < 4; j++)
#pragma unroll
            for (int v = 0; v < 4; v++) acc[i][j][v] = 0.0f;

    const int nt = K3 / GBK;

    auto load_stage = [&](int s, int t) {
        uint32_t sb = sBase + (uint32_t)s * STAGE_B;
        size_t koff = (size_t)t * GBK;
#pragma unroll
        for (int c = tid; c < BM * 4; c += 256) {
            int row = c >> 2, ch = c & 3;
            cpa16(sb + row * 80 + ch * 16,
                  A + (size_t)(bm0 + row) * K3 + koff + ch * 8, 16);
        }
#pragma unroll
        for (int c = tid; c < 512; c += 256) {
            int row = c >> 2, ch = c & 3;
            int br = bn0 + row;
            int bsz = (br < Nreal) ? 16 : 0;
            cpa16(sb + A_HALF + row * 80 + ch * 16,
                  B + (size_t)((br < Nreal) ? br : 0) * K3 + koff + ch * 8, bsz);
        }
    };

#pragma unroll
    for (int s = 0; s < NSTAGE - 1; s++) {
        if (s < nt) load_stage(s, s);
        cpa_commit();
    }

    for (int t = 0; t < nt; t++) {
        cpa_wait2();
        __syncthreads();

        int tn = t + NSTAGE - 1;
        if (tn < nt) load_stage(tn & (NSTAGE - 1), tn);
        cpa_commit();

        uint32_t aoff = sBase + (uint32_t)(t & (NSTAGE - 1)) * STAGE_B;
        uint32_t boff = aoff + A_HALF;
#pragma unroll
        for (int ks = 0; ks < 2; ks++) {
            uint32_t af[MT][4];
#pragma unroll
            for (int mt = 0; mt < MT; mt++)
                ldsm4(af[mt], aoff + ((wm + mt * 16 + lr) * GLDS + ks * 16 + lh * 8) * 2);
            uint32_t bf[2][4];
#pragma unroll
            for (int bt = 0; bt < 2; bt++)
                ldsm4(bf[bt], boff + ((wn + bt * 16 + lr) * GLDS + ks * 16 + lh * 8) * 2);
#pragma unroll
            for (int mt = 0; mt < MT; mt++) {
#pragma unroll
                for (int ntile = 0; ntile < 4; ntile++) {
                    int bt = ntile >> 1, sub = ntile & 1;
                    mma16816(acc[mt][ntile], af[mt], bf[bt][sub], bf[bt][sub + 2]);
                }
            }
        }
    }

    // epilogue: d0,d1 -> (m, n),(m, n+1); d2,d3 -> (m+8, n),(m+8, n+1)
    const int em = lane >> 2;
    const int en = (lane & 3) * 2;
#pragma unroll
    for (int mt = 0; mt < MT; mt++) {
#pragma unroll
        for (int ntile = 0; ntile < 4; ntile++) {
            int n = bn0 + wn + ntile * 8 + en;
            if (n >= Nreal) continue;
            int m = bm0 + wm + mt * 16 + em;
            float2 v0 = make_float2(acc[mt][ntile][0], acc[mt][ntile][1]);
            float2 v1 = make_float2(acc[mt][ntile][2], acc[mt][ntile][3]);
            if (bias) {
                float b0v = bias[n], b1v = bias[n + 1];
                v0.x += b0v; v0.y += b1v; v1.x += b0v; v1.y += b1v;
            }
            if (act == 1) {
                v0.x = softplusf(v0.x); v0.y = softplusf(v0.y);
                v1.x = softplusf(v1.x); v1.y = softplusf(v1.y);
            }
            *(float2*)(C + (size_t)m * ldc + n) = v0;
            *(float2*)(C + (size_t)(m + 8) * ldc + n) = v1;
            if (D3 && n < 48) {   // dt_low bf16-triple fused (A-side pattern)
                __nv_bfloat16 hi, lo;
                __nv_bfloat16* p0 = D3 + (size_t)m * K3_DT;
                split3(v0.x, hi, lo); p0[n] = hi; p0[64 + n] = lo; p0[128 + n] = hi;
                split3(v0.y, hi, lo); p0[n+1] = hi; p0[64 + n+1] = lo; p0[128 + n+1] = hi;
                __nv_bfloat16* p1 = D3 + (size_t)(m + 8) * K3_DT;
                split3(v1.x, hi, lo); p1[n] = hi; p1[64 + n] = lo; p1[128 + n] = hi;
                split3(v1.y, hi, lo); p1[n+1] = hi; p1[64 + n+1] = lo; p1[128 + n+1] = hi;
            }
        }
    }
}

// =============== causal depthwise conv + silu + bf16 triple ==============
__global__ void conv_silu_kernel(const float* __restrict__ xz,
                                 const float* __restrict__ cw, const float* __restrict__ cb,
                                 const float* __restrict__ cwb, const float* __restrict__ cbb,
                                 float* __restrict__ xcf, float* __restrict__ xcbk,
                                 __nv_bfloat16* __restrict__ xc3f,
                                 __nv_bfloat16* __restrict__ xc3b)
{
    int idx = blockIdx.x * blockDim.x + threadIdx.x;
    if (idx >= TT * DI) return;
    int d = idx % DI;
    int t = (idx / DI) % LL;
    int b = idx / (DI * LL);
    const float* xb = xz + (size_t)b * LL * NXZ + d;     // xs part, ld = 3072

    float accf = cb[d];
    if (t >= 3) accf = fmaf(xb[(size_t)(t - 3) * NXZ], cw[d * 4 + 0], accf);
    if (t >= 2) accf = fmaf(xb[(size_t)(t - 2) * NXZ], cw[d * 4 + 1], accf);
    if (t >= 1) accf = fmaf(xb[(size_t)(t - 1) * NXZ], cw[d * 4 + 2], accf);
    accf = fmaf(xb[(size_t)t * NXZ], cw[d * 4 + 3], accf);
    float vf = siluf(accf);

    int base = (LL - 1) - t;
    float accb = cbb[d];
    if (t >= 3) accb = fmaf(xb[(size_t)(base + 3) * NXZ], cwb[d * 4 + 0], accb);
    if (t >= 2) accb = fmaf(xb[(size_t)(base + 2) * NXZ], cwb[d * 4 + 1], accb);
    if (t >= 1) accb = fmaf(xb[(size_t)(base + 1) * NXZ], cwb[d * 4 + 2], accb);
    accb = fmaf(xb[(size_t)base * NXZ], cwb[d * 4 + 3], accb);
    float vb = siluf(accb);

    size_t r = (size_t)(b * LL + t);
    xcf[r * DI + d] = vf;
    xcbk[r * DI + d] = vb;
    __nv_bfloat16 hi, lo;
    split3(vf, hi, lo);
    __nv_bfloat16* d3 = xc3f + r * K3_BIG;
    d3[d] = hi; d3[DI + d] = lo; d3[2 * DI + d] = hi;
    split3(vb, hi, lo);
    d3 = xc3b + r * K3_BIG;
    d3[d] = hi; d3[DI + d] = lo; d3[2 * DI + d] = hi;
}

// ======================= selective scan ==================================
__global__ __launch_bounds__(256)
void scan_kernel(const float* __restrict__ xc0, const float* __restrict__ xc1,
                 const float* __restrict__ dl0, const float* __restrict__ dl1,
                 const float* __restrict__ pj0, const float* __restrict__ pj1,
                 const float* __restrict__ Alog0, const float* __restrict__ Alog1,
                 const float* __restrict__ Dp0, const float* __restrict__ Dp1,
                 float* __restrict__ y0, float* __restrict__ y1)
{
    int bid = blockIdx.x;
    int dgroup = bid % 96;
    int b = (bid / 96) % BB;
    int dir = bid / (96 * BB);

    const float* xc = dir ? xc1 : xc0;
    const float* dl = dir ? dl1 : dl0;
    const float* pj = dir ? pj1 : pj0;
    const float* Alog = dir ? Alog1 : Alog0;
    const float* Dp = dir ? Dp1 : Dp0;
    float* y = dir ? y1 : y0;

    int lane = threadIdx.x & 31;
    int w = threadIdx.x >> 5;
    int n = lane & 15;
    int d = dgroup * 16 + w * 2 + (lane >> 4);

    const float* xcp = xc + (size_t)b * LL * DI + d;
    const float* dlp = dl + (size_t)b * LL * DI + d;
    const float* pjB = pj + (size_t)b * LL * NPROJ + 48 + n;
    const float* pjC = pj + (size_t)b * LL * NPROJ + 64 + n;
    float* yp = y + (size_t)b * LL * DI + d;

    const float A = -__expf(Alog[d * DS + n]);
    const float Dd = Dp[d];

    float h = 0.0f;
    float dv = dlp[0], xv = xcp[0], Bv = pjB[0], Cv = pjC[0];

    for (int t = 0; t < LL; ++t) {
        float dv2 = 0.f, xv2 = 0.f, Bv2 = 0.f, Cv2 = 0.f;
        if (t + 1 < LL) {
            dv2 = dlp[(size_t)(t + 1) * DI];
            xv2 = xcp[(size_t)(t + 1) * DI];
            Bv2 = pjB[(size_t)(t + 1) * NPROJ];
            Cv2 = pjC[(size_t)(t + 1) * NPROJ];
        }
        float dA = __expf(dv * A);
        h = fmaf(dA, h, dv * xv * Bv);
        float p = h * Cv;
        p += __shfl_xor_sync(0xffffffffu, p, 1);
        p += __shfl_xor_sync(0xffffffffu, p, 2);
        p += __shfl_xor_sync(0xffffffffu, p, 4);
        p += __shfl_xor_sync(0xffffffffu, p, 8);
        if (n == 0) yp[(size_t)t * DI] = fmaf(Dd, xv, p);
        dv = dv2; xv = xv2; Bv = Bv2; Cv = Cv2;
    }
}

// ========== combine: 0.5*silu(z)*(y_f + rev(y_b)) -> bf16 triple ==========
__global__ void combine_kernel(const float* __restrict__ xz,
                               const float* __restrict__ yf,
                               const float* __restrict__ yb,
                               __nv_bfloat16* __restrict__ yc3)
{
    int idx = blockIdx.x * blockDim.x + threadIdx.x;
    if (idx >= TT * DI) return;
    int d = idx % DI;
    int l = (idx / DI) % LL;
    int b = idx / (DI * LL);
    float zz = xz[((size_t)b * LL + l) * NXZ + DI + d];
    float s = zz / (1.0f + __expf(-zz));
    float v = yf[idx] + yb[((size_t)b * LL + (LL - 1 - l)) * DI + d];
    v *= 0.5f * s;
    __nv_bfloat16 hi, lo; split3(v, hi, lo);
    __nv_bfloat16* d3 = yc3 + (size_t)(b * LL + l) * K3_BIG;
    d3[d] = hi; d3[DI + d] = lo; d3[2 * DI + d] = hi;
}

// ======================= launch ==========================================
extern "C" void kernel_launch(void* const* d_in, const int* in_sizes, int n_in,
                              void* d_out, int out_size)
{
    const float* x        = (const float*)d_in[0];
    const float* W_in_s   = (const float*)d_in[1];
    const float* W_in_g   = (const float*)d_in[2];
    const float* conv_w   = (const float*)d_in[3];
    const float* conv_b   = (const float*)d_in[4];
    const float* conv_w_b = (const float*)d_in[5];
    const float* conv_b_b = (const float*)d_in[6];
    const float* W_dt     = (const float*)d_in[7];
    const float* W_B      = (const float*)d_in[8];
    const float* W_C      = (const float*)d_in[9];
    const float* dtW      = (const float*)d_in[10];
    const float* dtb      = (const float*)d_in[11];
    const float* A_log    = (const float*)d_in[12];
    const float* Dp       = (const float*)d_in[13];
    const float* W_dt_b   = (const float*)d_in[14];
    const float* W_B_b    = (const float*)d_in[15];
    const float* W_C_b    = (const float*)d_in[16];
    const float* dtW_b    = (const float*)d_in[17];
    const float* dtb_b    = (const float*)d_in[18];
    const float* A_log_b  = (const float*)d_in[19];
    const float* Dp_b     = (const float*)d_in[20];
    const float* W_out    = (const float*)d_in[21];
    float* out = (float*)d_out;

    const int SMEM128 = NSTAGE * (128 * 80 + 128 * 80);   // 81920
    const int SMEM64  = NSTAGE * (64 * 80 + 128 * 80);    // 61440
    cudaFuncSetAttribute(gemm_mma<128>, cudaFuncAttributeMaxDynamicSharedMemorySize, SMEM128);
    cudaFuncSetAttribute(gemm_mma<64>,  cudaFuncAttributeMaxDynamicSharedMemorySize, SMEM64);

    float *p_xz, *p_xc, *p_wp, *p_pj, *p_dl, *p_y;
    __nv_bfloat16 *p_x3, *p_Wcat3, *p_xc3, *p_wp3, *p_pj3, *p_dtW3, *p_yc3, *p_Wout3;
    cudaGetSymbolAddress((void**)&p_xz, g_xz);
    cudaGetSymbolAddress((void**)&p_x3, g_x3);
    cudaGetSymbolAddress((void**)&p_Wcat3, g_Wcat3);
    cudaGetSymbolAddress((void**)&p_xc, g_xc);
    cudaGetSymbolAddress((void**)&p_xc3, g_xc3);
    cudaGetSymbolAddress((void**)&p_wp, g_wproj);
    cudaGetSymbolAddress((void**)&p_wp3, g_wproj3);
    cudaGetSymbolAddress((void**)&p_pj, g_pj);
    cudaGetSymbolAddress((void**)&p_pj3, g_pj3);
    cudaGetSymbolAddress((void**)&p_dtW3, g_dtW3);
    cudaGetSymbolAddress((void**)&p_dl, g_delta);
    cudaGetSymbolAddress((void**)&p_y, g_y);
    cudaGetSymbolAddress((void**)&p_yc3, g_yc3);
    cudaGetSymbolAddress((void**)&p_Wout3, g_Wout3);

    float* xc0 = p_xc;  float* xc1 = p_xc + (size_t)TT * DI;
    float* pj0 = p_pj;  float* pj1 = p_pj + (size_t)TT * NPROJ;
    float* dl0 = p_dl;  float* dl1 = p_dl + (size_t)TT * DI;
    float* y0  = p_y;   float* y1  = p_y + (size_t)TT * DI;
    float* wp0 = p_wp;  float* wp1 = p_wp + (size_t)NPROJ * DI;
    __nv_bfloat16* xc3f = p_xc3;
    __nv_bfloat16* xc3b = p_xc3 + (size_t)TT * K3_BIG;
    __nv_bfloat16* wp3f = p_wp3;
    __nv_bfloat16* wp3b = p_wp3 + (size_t)NPROJ * K3_BIG;
    __nv_bfloat16* pj3f = p_pj3;
    __nv_bfloat16* pj3b = p_pj3 + (size_t)TT * K3_DT;
    __nv_bfloat16* dtW3f = p_dtW3;
    __nv_bfloat16* dtW3b = p_dtW3 + (size_t)DI * K3_DT;

    const int EW = 256;
    const int nEW = (TT * DI + EW - 1) / EW;
    auto cgrid = [](int total) { return (total + 255) / 256; };

    // --- prep (exactly 5 launches so launch idx 5 = in-proj GEMM) ---
    concat_wproj<<<cgrid(NPROJ * DI), 256>>>(W_dt, W_B, W_C, W_dt_b, W_B_b, W_C_b, wp0, wp1);
    conv3_kernel<<<cgrid(DI * DM), 256>>>(W_in_s, DM, DM, DM, p_Wcat3, 0, DI * DM);
    conv3_kernel<<<cgrid(DI * DM), 256>>>(W_in_g, DM, DM, DM,
                                          p_Wcat3 + (size_t)DI * K3_IN, 0, DI * DM);
    prep_rest_kernel<<<1184, 256>>>(wp0, wp1, dtW, dtW_b, W_out,
                                    wp3f, wp3b, dtW3f, dtW3b, p_Wout3);
    conv3_kernel<<<cgrid(TT * DM), 256>>>(x, DM, DM, DM, p_x3, 1, TT * DM);

    // in-proj: xz[T,3072] = x3 @ Wcat3^T          (launch idx 5 — ncu capture)
    gemm_mma<128><<<dim3(NXZ / 128, TT / 128, 1), 256, SMEM128>>>(
        p_x3, p_x3, p_Wcat3, p_Wcat3, p_xz, p_xz, NXZ, K3_IN, NXZ,
        nullptr, nullptr, 0, nullptr, nullptr);

    // conv + silu + bf16 triple
    conv_silu_kernel<<<nEW, EW>>>(p_xz, conv_w, conv_b, conv_w_b, conv_b_b,
                                  xc0, xc1, xc3f, xc3b);

    // proj: pj[T,80] = xc3 @ wproj3^T (both dirs) + fused pj3 triple
    gemm_mma<64><<<dim3(1, TT / 64, 2), 256, SMEM64>>>(
        xc3f, xc3b, wp3f, wp3b, pj0, pj1, NPROJ, K3_BIG, NPROJ,
        nullptr, nullptr, 0, pj3f, pj3b);

    // delta = softplus(pj3 @ dtW3^T + dtb) (both dirs)
    gemm_mma<128><<<dim3(DI / 128, TT / 128, 2), 256, SMEM128>>>(
        pj3f, pj3b, dtW3f, dtW3b, dl0, dl1, DI, K3_DT, DI,
        dtb, dtb_b, 1, nullptr, nullptr);

    // selective scan
    scan_kernel<<<2 * BB * (DI / 16), 256>>>(
        xc0, xc1, dl0, dl1, pj0, pj1, A_log, A_log_b, Dp, Dp_b, y0, y1);

    // combine -> yc3 (bf16 triple)
    combine_kernel<<<nEW, EW>>>(p_xz, y0, y1, p_yc3);

    // out-proj: out[T,768] = yc3 @ Wout3^T  (BM=64 -> 192 CTAs)
    gemm_mma<64><<<dim3(DM / 128, TT / 64, 1), 256, SMEM64>>>(
        p_yc3, p_yc3, p_Wout3, p_Wout3, out, out, DM, K3_BIG, DM,
        nullptr, nullptr, 0, nullptr, nullptr);
}

// round 6
// speedup vs baseline: 1.2471x; 1.0014x over previous
#include <cuda_runtime.h>
#include <cuda_bf16.h>
#include <cstdint>
#include <cstddef>

#define DM 768
#define DI 1536
#define DS 16
#define DR 48
#define BB 2
#define LL 1024
#define TT (BB*LL)
#define NPROJ 80
#define NXZ 3072          // xs(1536) + z(1536) fused in-proj
#define K3_IN  2304       // 3*768
#define K3_BIG 4608       // 3*1536
#define K3_DT  192        // 3*64 (48 padded to 64)

// ======================= scratch (device globals) =======================
__device__ __align__(128) float g_xz[TT*NXZ];
__device__ __align__(128) __nv_bfloat16 g_x3[(size_t)TT*K3_IN];
__device__ __align__(128) __nv_bfloat16 g_Wcat3[(size_t)NXZ*K3_IN];
__device__ __align__(128) float g_xc[2][TT*DI];
__device__ __align__(128) __nv_bfloat16 g_xc3[2][(size_t)TT*K3_BIG];
__device__ __align__(128) float g_wproj[2][NPROJ*DI];
__device__ __align__(128) __nv_bfloat16 g_wproj3[2][(size_t)NPROJ*K3_BIG];
__device__ __align__(128) float g_pj[2][TT*NPROJ];
__device__ __align__(128) __nv_bfloat16 g_pj3[2][(size_t)TT*K3_DT];   // pad cols stay 0
__device__ __align__(128) __nv_bfloat16 g_dtW3[2][(size_t)DI*K3_DT];
__device__ __align__(128) float g_delta[2][TT*DI];
__device__ __align__(128) float g_y[2][TT*DI];
__device__ __align__(128) __nv_bfloat16 g_yc3[(size_t)TT*K3_BIG];
__device__ __align__(128) __nv_bfloat16 g_Wout3[(size_t)DM*K3_BIG];

__device__ __forceinline__ float siluf(float x) { return x / (1.0f + __expf(-x)); }
__device__ __forceinline__ float softplusf(float x) {
    return (x > 20.0f) ? x : log1pf(__expf(x));
}
__device__ __forceinline__ void split3(float v, __nv_bfloat16& hi, __nv_bfloat16& lo) {
    hi = __float2bfloat16(v);
    lo = __float2bfloat16(v - __bfloat162float(hi));
}

// =============== bf16-triple conversion: fp32[rows,K] -> bf16[rows,3*Kseg]
// isA: segs {hi, lo, hi};  !isA (B-side): segs {hi, hi, lo}
__global__ void conv3_kernel(const float* __restrict__ src, int lds, int Kreal,
                             int Kseg, __nv_bfloat16* __restrict__ dst, int isA,
                             int total)
{
    int idx = blockIdx.x * blockDim.x + threadIdx.x;
    if (idx >= total) return;
    int r = idx / Kseg, k = idx - r * Kseg;
    float v = (k < Kreal) ? src[(size_t)r * lds + k] : 0.0f;
    __nv_bfloat16 hi, lo; split3(v, hi, lo);
    size_t base = (size_t)r * 3 * Kseg;
    if (isA) { dst[base + k] = hi; dst[base + Kseg + k] = lo; dst[base + 2*Kseg + k] = hi; }
    else     { dst[base + k] = hi; dst[base + Kseg + k] = hi; dst[base + 2*Kseg + k] = lo; }
}

// =============== concat dt/B/C weights into [80,1536] per dir =============
__global__ void concat_wproj(const float* __restrict__ Wdt, const float* __restrict__ WB,
                             const float* __restrict__ WC,
                             const float* __restrict__ Wdtb, const float* __restrict__ WBb,
                             const float* __restrict__ WCb,
                             float* __restrict__ w0, float* __restrict__ w1)
{
    int i = blockIdx.x * blockDim.x + threadIdx.x;
    if (i >= NPROJ * DI) return;
    int r = i / DI, c = i % DI;
    float vf, vb;
    if (r < 48)      { vf = Wdt[r * DI + c];        vb = Wdtb[r * DI + c]; }
    else if (r < 64) { vf = WB[(r - 48) * DI + c];  vb = WBb[(r - 48) * DI + c]; }
    else             { vf = WC[(r - 64) * DI + c];  vb = WCb[(r - 64) * DI + c]; }
    w0[i] = vf; w1[i] = vb;
}

// =============== fused remaining weight conversions (B-side) ==============
#define RW0 (NPROJ*DI)
#define RW1 (2*NPROJ*DI)
#define RW2 (2*NPROJ*DI + DI*64)
#define RW3 (2*NPROJ*DI + 2*DI*64)
#define RWT (2*NPROJ*DI + 2*DI*64 + DM*DI)
__global__ void prep_rest_kernel(const float* __restrict__ wp0, const float* __restrict__ wp1,
                                 const float* __restrict__ dtW, const float* __restrict__ dtWb,
                                 const float* __restrict__ Wout,
                                 __nv_bfloat16* __restrict__ wp3f, __nv_bfloat16* __restrict__ wp3b,
                                 __nv_bfloat16* __restrict__ dtW3f, __nv_bfloat16* __restrict__ dtW3b,
                                 __nv_bfloat16* __restrict__ Wout3)
{
    for (int idx = blockIdx.x * blockDim.x + threadIdx.x; idx < RWT;
         idx += gridDim.x * blockDim.x) {
        const float* src; __nv_bfloat16* dst; int lds, Kreal, Kseg, local;
        if (idx < RW0)      { local = idx;       src = wp0;  dst = wp3f;  lds = DI; Kreal = DI; Kseg = DI; }
        else if (idx < RW1) { local = idx - RW0; src = wp1;  dst = wp3b;  lds = DI; Kreal = DI; Kseg = DI; }
        else if (idx < RW2) { local = idx - RW1; src = dtW;  dst = dtW3f; lds = DR; Kreal = DR; Kseg = 64; }
        else if (idx < RW3) { local = idx - RW2; src = dtWb; dst = dtW3b; lds = DR; Kreal = DR; Kseg = 64; }
        else                { local = idx - RW3; src = Wout; dst = Wout3; lds = DI; Kreal = DI; Kseg = DI; }
        int r = local / Kseg, k = local - r * Kseg;
        float v = (k < Kreal) ? src[(size_t)r * lds + k] : 0.0f;
        __nv_bfloat16 hi, lo; split3(v, hi, lo);
        size_t base = (size_t)r * 3 * Kseg;
        dst[base + k] = hi; dst[base + Kseg + k] = hi; dst[base + 2*Kseg + k] = lo;
    }
}

// ======================= mma.sync bf16 NT GEMM (cp.async 4-stage) =========
// C[z][2048, Nreal] = A3[z][2048, K3] * B3[z][Npad, K3]^T  (bf16 in, fp32 acc)
// 64 x 128 x 32 tile, 8 warps (2x4), 32x32 per warp, m16n8k16 HMMA.
#define BM 64
#define GBK 32
#define GLDS 40                  // padded row stride (bf16): 32 + 8
#define NSTAGE 4
#define A_HALF (BM*80)           // bytes per A stage = 5120
#define STAGE_B (A_HALF + 128*80) // bytes per stage (A+B) = 15360
#define GSMEM (NSTAGE*STAGE_B)   // 61440
#define MT 2                     // m16 tiles per warp

__device__ __forceinline__ void ldsm4(uint32_t* r, uint32_t addr) {
    asm volatile("ldmatrix.sync.aligned.m8n8.x4.shared.b16 {%0,%1,%2,%3}, [%4];"
                 : "=r"(r[0]), "=r"(r[1]), "=r"(r[2]), "=r"(r[3]) : "r"(addr));
}
__device__ __forceinline__ void mma16816(float* d, const uint32_t* a,
                                         uint32_t b0, uint32_t b1) {
    asm volatile("mma.sync.aligned.m16n8k16.row.col.f32.bf16.bf16.f32 "
                 "{%0,%1,%2,%3}, {%4,%5,%6,%7}, {%8,%9}, {%0,%1,%2,%3};"
                 : "+f"(d[0]), "+f"(d[1]), "+f"(d[2]), "+f"(d[3])
                 : "r"(a[0]), "r"(a[1]), "r"(a[2]), "r"(a[3]), "r"(b0), "r"(b1));
}
__device__ __forceinline__ void cpa16(uint32_t dst, const void* src, int sz) {
    asm volatile("cp.async.cg.shared.global [%0], [%1], 16, %2;"
                 :: "r"(dst), "l"(src), "r"(sz) : "memory");
}
__device__ __forceinline__ void cpa_commit() {
    asm volatile("cp.async.commit_group;" ::: "memory");
}
__device__ __forceinline__ void cpa_wait2() {
    asm volatile("cp.async.wait_group 2;" ::: "memory");
}

__global__ __launch_bounds__(256, 3)
void gemm_mma(const __nv_bfloat16* __restrict__ A0, const __nv_bfloat16* __restrict__ A1,
              const __nv_bfloat16* __restrict__ B0, const __nv_bfloat16* __restrict__ B1,
              float* __restrict__ C0, float* __restrict__ C1,
              int ldc, int K3, int Nreal,
              const float* __restrict__ bias0, const float* __restrict__ bias1, int act,
              __nv_bfloat16* __restrict__ D30, __nv_bfloat16* __restrict__ D31)
{
    extern __shared__ char smem[];

    const int z = blockIdx.z;
    const __nv_bfloat16* A = z ? A1 : A0;
    const __nv_bfloat16* B = z ? B1 : B0;
    float* C = z ? C1 : C0;
    const float* bias = z ? bias1 : bias0;
    __nv_bfloat16* D3 = z ? D31 : D30;

    const int tid = threadIdx.x;
    const int lane = tid & 31;
    const int wid = tid >> 5;
    const int bm0 = blockIdx.y * BM;
    const int bn0 = blockIdx.x * 128;
    const int wm = (wid >> 2) * 32;     // 0 or 32
    const int wn = (wid & 3) * 32;      // 0,32,64,96

    const uint32_t sBase = (uint32_t)__cvta_generic_to_shared(smem);
    const int lr = lane & 15, lh = lane >> 4;

    float acc[MT][4][4];
#pragma unroll
    for (int i = 0; i < MT; i++)
#pragma unroll
        for (int j = 0; j < 4; j++)
#pragma unroll
            for (int v = 0; v < 4; v++) acc[i][j][v] = 0.0f;

    const int nt = K3 / GBK;

    auto load_stage = [&](int s, int t) {
        uint32_t sb = sBase + (uint32_t)s * STAGE_B;
        size_t koff = (size_t)t * GBK;
        {   // A: 64 rows x 4 chunks = 256 = one chunk per thread
            int row = tid >> 2, ch = tid & 3;
            cpa16(sb + row * 80 + ch * 16,
                  A + (size_t)(bm0 + row) * K3 + koff + ch * 8, 16);
        }
#pragma unroll
        for (int c = tid; c < 512; c += 256) {   // B: 128 rows x 4 chunks
            int row = c >> 2, ch = c & 3;
            int br = bn0 + row;
            int bsz = (br < Nreal) ? 16 : 0;
            cpa16(sb + A_HALF + row * 80 + ch * 16,
                  B + (size_t)((br < Nreal) ? br : 0) * K3 + koff + ch * 8, bsz);
        }
    };

#pragma unroll
    for (int s = 0; s < NSTAGE - 1; s++) {
        if (s < nt) load_stage(s, s);
        cpa_commit();
    }

    for (int t = 0; t < nt; t++) {
        cpa_wait2();
        __syncthreads();

        int tn = t + NSTAGE - 1;
        if (tn < nt) load_stage(tn & (NSTAGE - 1), tn);
        cpa_commit();

        uint32_t aoff = sBase + (uint32_t)(t & (NSTAGE - 1)) * STAGE_B;
        uint32_t boff = aoff + A_HALF;
#pragma unroll
        for (int ks = 0; ks < 2; ks++) {
            uint32_t af[MT][4];
#pragma unroll
            for (int mt = 0; mt < MT; mt++)
                ldsm4(af[mt], aoff + ((wm + mt * 16 + lr) * GLDS + ks * 16 + lh * 8) * 2);
            uint32_t bf[2][4];
#pragma unroll
            for (int bt = 0; bt < 2; bt++)
                ldsm4(bf[bt], boff + ((wn + bt * 16 + lr) * GLDS + ks * 16 + lh * 8) * 2);
#pragma unroll
            for (int mt = 0; mt < MT; mt++) {
#pragma unroll
                for (int ntile = 0; ntile < 4; ntile++) {
                    int bt = ntile >> 1, sub = ntile & 1;
                    mma16816(acc[mt][ntile], af[mt], bf[bt][sub], bf[bt][sub + 2]);
                }
            }
        }
    }

    // epilogue: d0,d1 -> (m, n),(m, n+1); d2,d3 -> (m+8, n),(m+8, n+1)
    const int em = lane >> 2;
    const int en = (lane & 3) * 2;
#pragma unroll
    for (int mt = 0; mt < MT; mt++) {
#pragma unroll
        for (int ntile = 0; ntile < 4; ntile++) {
            int n = bn0 + wn + ntile * 8 + en;
            if (n >= Nreal) continue;
            int m = bm0 + wm + mt * 16 + em;
            float2 v0 = make_float2(acc[mt][ntile][0], acc[mt][ntile][1]);
            float2 v1 = make_float2(acc[mt][ntile][2], acc[mt][ntile][3]);
            if (bias) {
                float b0v = bias[n], b1v = bias[n + 1];
                v0.x += b0v; v0.y += b1v; v1.x += b0v; v1.y += b1v;
            }
            if (act == 1) {
                v0.x = softplusf(v0.x); v0.y = softplusf(v0.y);
                v1.x = softplusf(v1.x); v1.y = softplusf(v1.y);
            }
            *(float2*)(C + (size_t)m * ldc + n) = v0;
            *(float2*)(C + (size_t)(m + 8) * ldc + n) = v1;
            if (D3 && n < 48) {   // dt_low bf16-triple fused (A-side pattern)
                __nv_bfloat16 hi, lo;
                __nv_bfloat16* p0 = D3 + (size_t)m * K3_DT;
                split3(v0.x, hi, lo); p0[n] = hi; p0[64 + n] = lo; p0[128 + n] = hi;
                split3(v0.y, hi, lo); p0[n+1] = hi; p0[64 + n+1] = lo; p0[128 + n+1] = hi;
                __nv_bfloat16* p1 = D3 + (size_t)(m + 8) * K3_DT;
                split3(v1.x, hi, lo); p1[n] = hi; p1[64 + n] = lo; p1[128 + n] = hi;
                split3(v1.y, hi, lo); p1[n+1] = hi; p1[64 + n+1] = lo; p1[128 + n+1] = hi;
            }
        }
    }
}

// =============== causal depthwise conv + silu + bf16 triple ==============
__global__ void conv_silu_kernel(const float* __restrict__ xz,
                                 const float* __restrict__ cw, const float* __restrict__ cb,
                                 const float* __restrict__ cwb, const float* __restrict__ cbb,
                                 float* __restrict__ xcf, float* __restrict__ xcbk,
                                 __nv_bfloat16* __restrict__ xc3f,
                                 __nv_bfloat16* __restrict__ xc3b)
{
    int idx = blockIdx.x * blockDim.x + threadIdx.x;
    if (idx >= TT * DI) return;
    int d = idx % DI;
    int t = (idx / DI) % LL;
    int b = idx / (DI * LL);
    const float* xb = xz + (size_t)b * LL * NXZ + d;     // xs part, ld = 3072

    float accf = cb[d];
    if (t >= 3) accf = fmaf(xb[(size_t)(t - 3) * NXZ], cw[d * 4 + 0], accf);
    if (t >= 2) accf = fmaf(xb[(size_t)(t - 2) * NXZ], cw[d * 4 + 1], accf);
    if (t >= 1) accf = fmaf(xb[(size_t)(t - 1) * NXZ], cw[d * 4 + 2], accf);
    accf = fmaf(xb[(size_t)t * NXZ], cw[d * 4 + 3], accf);
    float vf = siluf(accf);

    int base = (LL - 1) - t;
    float accb = cbb[d];
    if (t >= 3) accb = fmaf(xb[(size_t)(base + 3) * NXZ], cwb[d * 4 + 0], accb);
    if (t >= 2) accb = fmaf(xb[(size_t)(base + 2) * NXZ], cwb[d * 4 + 1], accb);
    if (t >= 1) accb = fmaf(xb[(size_t)(base + 1) * NXZ], cwb[d * 4 + 2], accb);
    accb = fmaf(xb[(size_t)base * NXZ], cwb[d * 4 + 3], accb);
    float vb = siluf(accb);

    size_t r = (size_t)(b * LL + t);
    xcf[r * DI + d] = vf;
    xcbk[r * DI + d] = vb;
    __nv_bfloat16 hi, lo;
    split3(vf, hi, lo);
    __nv_bfloat16* d3 = xc3f + r * K3_BIG;
    d3[d] = hi; d3[DI + d] = lo; d3[2 * DI + d] = hi;
    split3(vb, hi, lo);
    d3 = xc3b + r * K3_BIG;
    d3[d] = hi; d3[DI + d] = lo; d3[2 * DI + d] = hi;
}

// ======================= selective scan ==================================
__global__ __launch_bounds__(256)
void scan_kernel(const float* __restrict__ xc0, const float* __restrict__ xc1,
                 const float* __restrict__ dl0, const float* __restrict__ dl1,
                 const float* __restrict__ pj0, const float* __restrict__ pj1,
                 const float* __restrict__ Alog0, const float* __restrict__ Alog1,
                 const float* __restrict__ Dp0, const float* __restrict__ Dp1,
                 float* __restrict__ y0, float* __restrict__ y1)
{
    int bid = blockIdx.x;
    int dgroup = bid % 96;
    int b = (bid / 96) % BB;
    int dir = bid / (96 * BB);

    const float* xc = dir ? xc1 : xc0;
    const float* dl = dir ? dl1 : dl0;
    const float* pj = dir ? pj1 : pj0;
    const float* Alog = dir ? Alog1 : Alog0;
    const float* Dp = dir ? Dp1 : Dp0;
    float* y = dir ? y1 : y0;

    int lane = threadIdx.x & 31;
    int w = threadIdx.x >> 5;
    int n = lane & 15;
    int d = dgroup * 16 + w * 2 + (lane >> 4);

    const float* xcp = xc + (size_t)b * LL * DI + d;
    const float* dlp = dl + (size_t)b * LL * DI + d;
    const float* pjB = pj + (size_t)b * LL * NPROJ + 48 + n;
    const float* pjC = pj + (size_t)b * LL * NPROJ + 64 + n;
    float* yp = y + (size_t)b * LL * DI + d;

    const float A = -__expf(Alog[d * DS + n]);
    const float Dd = Dp[d];

    float h = 0.0f;
    float dv = dlp[0], xv = xcp[0], Bv = pjB[0], Cv = pjC[0];

    for (int t = 0; t < LL; ++t) {
        float dv2 = 0.f, xv2 = 0.f, Bv2 = 0.f, Cv2 = 0.f;
        if (t + 1 < LL) {
            dv2 = dlp[(size_t)(t + 1) * DI];
            xv2 = xcp[(size_t)(t + 1) * DI];
            Bv2 = pjB[(size_t)(t + 1) * NPROJ];
            Cv2 = pjC[(size_t)(t + 1) * NPROJ];
        }
        float dA = __expf(dv * A);
        h = fmaf(dA, h, dv * xv * Bv);
        float p = h * Cv;
        p += __shfl_xor_sync(0xffffffffu, p, 1);
        p += __shfl_xor_sync(0xffffffffu, p, 2);
        p += __shfl_xor_sync(0xffffffffu, p, 4);
        p += __shfl_xor_sync(0xffffffffu, p, 8);
        if (n == 0) yp[(size_t)t * DI] = fmaf(Dd, xv, p);
        dv = dv2; xv = xv2; Bv = Bv2; Cv = Cv2;
    }
}

// ========== combine: 0.5*silu(z)*(y_f + rev(y_b)) -> bf16 triple ==========
__global__ void combine_kernel(const float* __restrict__ xz,
                               const float* __restrict__ yf,
                               const float* __restrict__ yb,
                               __nv_bfloat16* __restrict__ yc3)
{
    int idx = blockIdx.x * blockDim.x + threadIdx.x;
    if (idx >= TT * DI) return;
    int d = idx % DI;
    int l = (idx / DI) % LL;
    int b = idx / (DI * LL);
    float zz = xz[((size_t)b * LL + l) * NXZ + DI + d];
    float s = zz / (1.0f + __expf(-zz));
    float v = yf[idx] + yb[((size_t)b * LL + (LL - 1 - l)) * DI + d];
    v *= 0.5f * s;
    __nv_bfloat16 hi, lo; split3(v, hi, lo);
    __nv_bfloat16* d3 = yc3 + (size_t)(b * LL + l) * K3_BIG;
    d3[d] = hi; d3[DI + d] = lo; d3[2 * DI + d] = hi;
}

// ======================= launch ==========================================
extern "C" void kernel_launch(void* const* d_in, const int* in_sizes, int n_in,
                              void* d_out, int out_size)
{
    const float* x        = (const float*)d_in[0];
    const float* W_in_s   = (const float*)d_in[1];
    const float* W_in_g   = (const float*)d_in[2];
    const float* conv_w   = (const float*)d_in[3];
    const float* conv_b   = (const float*)d_in[4];
    const float* conv_w_b = (const float*)d_in[5];
    const float* conv_b_b = (const float*)d_in[6];
    const float* W_dt     = (const float*)d_in[7];
    const float* W_B      = (const float*)d_in[8];
    const float* W_C      = (const float*)d_in[9];
    const float* dtW      = (const float*)d_in[10];
    const float* dtb      = (const float*)d_in[11];
    const float* A_log    = (const float*)d_in[12];
    const float* Dp       = (const float*)d_in[13];
    const float* W_dt_b   = (const float*)d_in[14];
    const float* W_B_b    = (const float*)d_in[15];
    const float* W_C_b    = (const float*)d_in[16];
    const float* dtW_b    = (const float*)d_in[17];
    const float* dtb_b    = (const float*)d_in[18];
    const float* A_log_b  = (const float*)d_in[19];
    const float* Dp_b     = (const float*)d_in[20];
    const float* W_out    = (const float*)d_in[21];
    float* out = (float*)d_out;

    cudaFuncSetAttribute(gemm_mma, cudaFuncAttributeMaxDynamicSharedMemorySize, GSMEM);

    float *p_xz, *p_xc, *p_wp, *p_pj, *p_dl, *p_y;
    __nv_bfloat16 *p_x3, *p_Wcat3, *p_xc3, *p_wp3, *p_pj3, *p_dtW3, *p_yc3, *p_Wout3;
    cudaGetSymbolAddress((void**)&p_xz, g_xz);
    cudaGetSymbolAddress((void**)&p_x3, g_x3);
    cudaGetSymbolAddress((void**)&p_Wcat3, g_Wcat3);
    cudaGetSymbolAddress((void**)&p_xc, g_xc);
    cudaGetSymbolAddress((void**)&p_xc3, g_xc3);
    cudaGetSymbolAddress((void**)&p_wp, g_wproj);
    cudaGetSymbolAddress((void**)&p_wp3, g_wproj3);
    cudaGetSymbolAddress((void**)&p_pj, g_pj);
    cudaGetSymbolAddress((void**)&p_pj3, g_pj3);
    cudaGetSymbolAddress((void**)&p_dtW3, g_dtW3);
    cudaGetSymbolAddress((void**)&p_dl, g_delta);
    cudaGetSymbolAddress((void**)&p_y, g_y);
    cudaGetSymbolAddress((void**)&p_yc3, g_yc3);
    cudaGetSymbolAddress((void**)&p_Wout3, g_Wout3);

    float* xc0 = p_xc;  float* xc1 = p_xc + (size_t)TT * DI;
    float* pj0 = p_pj;  float* pj1 = p_pj + (size_t)TT * NPROJ;
    float* dl0 = p_dl;  float* dl1 = p_dl + (size_t)TT * DI;
    float* y0  = p_y;   float* y1  = p_y + (size_t)TT * DI;
    float* wp0 = p_wp;  float* wp1 = p_wp + (size_t)NPROJ * DI;
    __nv_bfloat16* xc3f = p_xc3;
    __nv_bfloat16* xc3b = p_xc3 + (size_t)TT * K3_BIG;
    __nv_bfloat16* wp3f = p_wp3;
    __nv_bfloat16* wp3b = p_wp3 + (size_t)NPROJ * K3_BIG;
    __nv_bfloat16* pj3f = p_pj3;
    __nv_bfloat16* pj3b = p_pj3 + (size_t)TT * K3_DT;
    __nv_bfloat16* dtW3f = p_dtW3;
    __nv_bfloat16* dtW3b = p_dtW3 + (size_t)DI * K3_DT;

    const int EW = 256;
    const int nEW = (TT * DI + EW - 1) / EW;
    auto cgrid = [](int total) { return (total + 255) / 256; };

    // --- in-proj prerequisites only, so the GEMM is OUR launch idx 3 ---
    conv3_kernel<<<cgrid(TT * DM), 256>>>(x, DM, DM, DM, p_x3, 1, TT * DM);
    conv3_kernel<<<cgrid(DI * DM), 256>>>(W_in_s, DM, DM, DM, p_Wcat3, 0, DI * DM);
    conv3_kernel<<<cgrid(DI * DM), 256>>>(W_in_g, DM, DM, DM,
                                          p_Wcat3 + (size_t)DI * K3_IN, 0, DI * DM);

    // in-proj: xz[T,3072] = x3 @ Wcat3^T          (our idx 3 — ncu capture)
    gemm_mma<<<dim3(NXZ / 128, TT / BM, 1), 256, GSMEM>>>(
        p_x3, p_x3, p_Wcat3, p_Wcat3, p_xz, p_xz, NXZ, K3_IN, NXZ,
        nullptr, nullptr, 0, nullptr, nullptr);

    // remaining weight prep (overlaps nothing, but independent of in-proj)
    concat_wproj<<<cgrid(NPROJ * DI), 256>>>(W_dt, W_B, W_C, W_dt_b, W_B_b, W_C_b, wp0, wp1);
    prep_rest_kernel<<<1184, 256>>>(wp0, wp1, dtW, dtW_b, W_out,
                                    wp3f, wp3b, dtW3f, dtW3b, p_Wout3);

    // conv + silu + bf16 triple
    conv_silu_kernel<<<nEW, EW>>>(p_xz, conv_w, conv_b, conv_w_b, conv_b_b,
                                  xc0, xc1, xc3f, xc3b);

    // proj: pj[T,80] = xc3 @ wproj3^T (both dirs) + fused pj3 triple
    gemm_mma<<<dim3(1, TT / BM, 2), 256, GSMEM>>>(
        xc3f, xc3b, wp3f, wp3b, pj0, pj1, NPROJ, K3_BIG, NPROJ,
        nullptr, nullptr, 0, pj3f, pj3b);

    // delta = softplus(pj3 @ dtW3^T + dtb) (both dirs)
    gemm_mma<<<dim3(DI / 128, TT / BM, 2), 256, GSMEM>>>(
        pj3f, pj3b, dtW3f, dtW3b, dl0, dl1, DI, K3_DT, DI,
        dtb, dtb_b, 1, nullptr, nullptr);

    // selective scan
    scan_kernel<<<2 * BB * (DI / 16), 256>>>(
        xc0, xc1, dl0, dl1, pj0, pj1, A_log, A_log_b, Dp, Dp_b, y0, y1);

    // combine -> yc3 (bf16 triple)
    combine_kernel<<<nEW, EW>>>(p_xz, y0, y1, p_yc3);

    // out-proj: out[T,768] = yc3 @ Wout3^T
    gemm_mma<<<dim3(DM / 128, TT / BM, 1), 256, GSMEM>>>(
        p_yc3, p_yc3, p_Wout3, p_Wout3, out, out, DM, K3_BIG, DM,
        nullptr, nullptr, 0, nullptr, nullptr);
}

// round 7
// speedup vs baseline: 1.4277x; 1.1448x over previous
#include <cuda_runtime.h>
#include <cuda_fp16.h>
#include <cstdint>
#include <cstddef>

#define DM 768
#define DI 1536
#define DS 16
#define DR 48
#define BB 2
#define LL 1024
#define TT (BB*LL)
#define NPROJ 80
#define NXZ 3072          // xs(1536) + z(1536) fused in-proj
#define K2_IN  1536       // 2*768
#define K2_BIG 3072       // 2*1536
#define K2_DT  128        // 2*64 (48 padded to 64)

// ======================= scratch (device globals) =======================
__device__ __align__(128) float g_xz[TT*NXZ];
__device__ __align__(128) __half g_x2[(size_t)TT*K2_IN];
__device__ __align__(128) __half g_Wcat2[(size_t)NXZ*K2_IN];
__device__ __align__(128) float g_xc[2][TT*DI];
__device__ __align__(128) __half g_xc2[2][(size_t)TT*K2_BIG];
__device__ __align__(128) float g_wproj[2][NPROJ*DI];
__device__ __align__(128) __half g_wproj2[2][(size_t)NPROJ*K2_BIG];
__device__ __align__(128) float g_pj[2][TT*NPROJ];
__device__ __align__(128) __half g_pj2[2][(size_t)TT*K2_DT];   // pad cols stay 0
__device__ __align__(128) __half g_dtW2[2][(size_t)DI*K2_DT];
__device__ __align__(128) float g_delta[2][TT*DI];
__device__ __align__(128) float g_y[2][TT*DI];
__device__ __align__(128) __half g_yc2[(size_t)TT*K2_BIG];
__device__ __align__(128) __half g_Wout2[(size_t)DM*K2_BIG];

__device__ __forceinline__ float siluf(float x) { return x / (1.0f + __expf(-x)); }
__device__ __forceinline__ float softplusf(float x) {
    return (x > 20.0f) ? x : log1pf(__expf(x));
}
__device__ __forceinline__ void split2(float v, __half& hi, __half& lo) {
    hi = __float2half_rn(v);
    lo = __float2half_rn(v - __half2float(hi));
}

// =============== fp16-double conversion: fp32[rows,K] -> fp16[rows,2*Kseg]
// isA: segs {hi, lo};  !isA (B-side): segs {hi, hi}
// sum over 2K of A2*B2 = hi*hi + lo*hi  (compensated fp16x2 product)
__global__ void conv2_kernel(const float* __restrict__ src, int lds, int Kreal,
                             int Kseg, __half* __restrict__ dst, int isA,
                             int total)
{
    int idx = blockIdx.x * blockDim.x + threadIdx.x;
    if (idx >= total) return;
    int r = idx / Kseg, k = idx - r * Kseg;
    float v = (k < Kreal) ? src[(size_t)r * lds + k] : 0.0f;
    __half hi, lo; split2(v, hi, lo);
    size_t base = (size_t)r * 2 * Kseg;
    if (isA) { dst[base + k] = hi; dst[base + Kseg + k] = lo; }
    else     { dst[base + k] = hi; dst[base + Kseg + k] = hi; }
}

// =============== concat dt/B/C weights into [80,1536] per dir =============
__global__ void concat_wproj(const float* __restrict__ Wdt, const float* __restrict__ WB,
                             const float* __restrict__ WC,
                             const float* __restrict__ Wdtb, const float* __restrict__ WBb,
                             const float* __restrict__ WCb,
                             float* __restrict__ w0, float* __restrict__ w1)
{
    int i = blockIdx.x * blockDim.x + threadIdx.x;
    if (i >= NPROJ * DI) return;
    int r = i / DI, c = i % DI;
    float vf, vb;
    if (r < 48)      { vf = Wdt[r * DI + c];        vb = Wdtb[r * DI + c]; }
    else if (r < 64) { vf = WB[(r - 48) * DI + c];  vb = WBb[(r - 48) * DI + c]; }
    else             { vf = WC[(r - 64) * DI + c];  vb = WCb[(r - 64) * DI + c]; }
    w0[i] = vf; w1[i] = vb;
}

// =============== fused remaining weight conversions (B-side) ==============
#define RW0 (NPROJ*DI)
#define RW1 (2*NPROJ*DI)
#define RW2 (2*NPROJ*DI + DI*64)
#define RW3 (2*NPROJ*DI + 2*DI*64)
#define RWT (2*NPROJ*DI + 2*DI*64 + DM*DI)
__global__ void prep_rest_kernel(const float* __restrict__ wp0, const float* __restrict__ wp1,
                                 const float* __restrict__ dtW, const float* __restrict__ dtWb,
                                 const float* __restrict__ Wout,
                                 __half* __restrict__ wp2f, __half* __restrict__ wp2b,
                                 __half* __restrict__ dtW2f, __half* __restrict__ dtW2b,
                                 __half* __restrict__ Wout2)
{
    for (int idx = blockIdx.x * blockDim.x + threadIdx.x; idx < RWT;
         idx += gridDim.x * blockDim.x) {
        const float* src; __half* dst; int lds, Kreal, Kseg, local;
        if (idx < RW0)      { local = idx;       src = wp0;  dst = wp2f;  lds = DI; Kreal = DI; Kseg = DI; }
        else if (idx < RW1) { local = idx - RW0; src = wp1;  dst = wp2b;  lds = DI; Kreal = DI; Kseg = DI; }
        else if (idx < RW2) { local = idx - RW1; src = dtW;  dst = dtW2f; lds = DR; Kreal = DR; Kseg = 64; }
        else if (idx < RW3) { local = idx - RW2; src = dtWb; dst = dtW2b; lds = DR; Kreal = DR; Kseg = 64; }
        else                { local = idx - RW3; src = Wout; dst = Wout2; lds = DI; Kreal = DI; Kseg = DI; }
        int r = local / Kseg, k = local - r * Kseg;
        float v = (k < Kreal) ? src[(size_t)r * lds + k] : 0.0f;
        __half hi, lo; split2(v, hi, lo);
        size_t base = (size_t)r * 2 * Kseg;
        dst[base + k] = hi; dst[base + Kseg + k] = hi;
    }
}

// ======================= mma.sync fp16 NT GEMM (cp.async 4-stage) =========
// C[z][2048, Nreal] = A2[z][2048, K2] * B2[z][Npad, K2]^T  (fp16 in, fp32 acc)
// 64 x 128 x 32 tile, 8 warps (2x4), 32x32 per warp, m16n8k16 HMMA.
#define BM 64
#define GBK 32
#define GLDS 40                  // padded row stride (fp16): 32 + 8
#define NSTAGE 4
#define A_HALF (BM*80)           // bytes per A stage = 5120
#define STAGE_B (A_HALF + 128*80) // bytes per stage (A+B) = 15360
#define GSMEM (NSTAGE*STAGE_B)   // 61440
#define MT 2                     // m16 tiles per warp

__device__ __forceinline__ void ldsm4(uint32_t* r, uint32_t addr) {
    asm volatile("ldmatrix.sync.aligned.m8n8.x4.shared.b16 {%0,%1,%2,%3}, [%4];"
                 : "=r"(r[0]), "=r"(r[1]), "=r"(r[2]), "=r"(r[3]) : "r"(addr));
}
__device__ __forceinline__ void mma16816(float* d, const uint32_t* a,
                                         uint32_t b0, uint32_t b1) {
    asm volatile("mma.sync.aligned.m16n8k16.row.col.f32.f16.f16.f32 "
                 "{%0,%1,%2,%3}, {%4,%5,%6,%7}, {%8,%9}, {%0,%1,%2,%3};"
                 : "+f"(d[0]), "+f"(d[1]), "+f"(d[2]), "+f"(d[3])
                 : "r"(a[0]), "r"(a[1]), "r"(a[2]), "r"(a[3]), "r"(b0), "r"(b1));
}
__device__ __forceinline__ void cpa16(uint32_t dst, const void* src, int sz) {
    asm volatile("cp.async.cg.shared.global [%0], [%1], 16, %2;"
                 :: "r"(dst), "l"(src), "r"(sz) : "memory");
}
__device__ __forceinline__ void cpa_commit() {
    asm volatile("cp.async.commit_group;" ::: "memory");
}
__device__ __forceinline__ void cpa_wait2() {
    asm volatile("cp.async.wait_group 2;" ::: "memory");
}

__global__ __launch_bounds__(256, 3)
void gemm_mma(const __half* __restrict__ A0, const __half* __restrict__ A1,
              const __half* __restrict__ B0, const __half* __restrict__ B1,
              float* __restrict__ C0, float* __restrict__ C1,
              int ldc, int K2, int Nreal,
              const float* __restrict__ bias0, const float* __restrict__ bias1, int act,
              __half* __restrict__ D20, __half* __restrict__ D21)
{
    extern __shared__ char smem[];

    const int z = blockIdx.z;
    const __half* A = z ? A1 : A0;
    const __half* B = z ? B1 : B0;
    float* C = z ? C1 : C0;
    const float* bias = z ? bias1 : bias0;
    __half* D2 = z ? D21 : D20;

    const int tid = threadIdx.x;
    const int lane = tid & 31;
    const int wid = tid >> 5;
    const int bm0 = blockIdx.y * BM;
    const int bn0 = blockIdx.x * 128;
    const int wm = (wid >> 2) * 32;     // 0 or 32
    const int wn = (wid & 3) * 32;      // 0,32,64,96

    const uint32_t sBase = (uint32_t)__cvta_generic_to_shared(smem);
    const int lr = lane & 15, lh = lane >> 4;

    float acc[MT][4][4];
#pragma unroll
    for (int i = 0; i < MT; i++)
#pragma unroll
        for (int j = 0; j < 4; j++)
#pragma unroll
            for (int v = 0; v < 4; v++) acc[i][j][v] = 0.0f;

    const int nt = K2 / GBK;

    // incrementally-advanced global pointers (less per-iter IMAD)
    const int arow = tid >> 2, ach = tid & 3;
    const __half* Ap = A + (size_t)(bm0 + arow) * K2 + ach * 8;
    const int brow0 = bn0 + arow;
    const int brow1 = bn0 + arow + 64;
    const int bsz0 = (brow0 < Nreal) ? 16 : 0;
    const int bsz1 = (brow1 < Nreal) ? 16 : 0;
    const __half* Bp0 = B + (size_t)((brow0 < Nreal) ? brow0 : 0) * K2 + ach * 8;
    const __half* Bp1 = B + (size_t)((brow1 < Nreal) ? brow1 : 0) * K2 + ach * 8;
    const uint32_t sA = (uint32_t)(arow * 80 + ach * 16);
    const uint32_t sB0 = A_HALF + sA;
    const uint32_t sB1 = A_HALF + sA + 64 * 80;

    auto load_stage = [&](int s, int t) {
        uint32_t sb = sBase + (uint32_t)s * STAGE_B;
        size_t koff = (size_t)t * GBK;
        cpa16(sb + sA, Ap + koff, 16);
        cpa16(sb + sB0, Bp0 + koff, bsz0);
        cpa16(sb + sB1, Bp1 + koff, bsz1);
    };

#pragma unroll
    for (int s = 0; s < NSTAGE - 1; s++) {
        if (s < nt) load_stage(s, s);
        cpa_commit();
    }

    for (int t = 0; t < nt; t++) {
        cpa_wait2();
        __syncthreads();

        int tn = t + NSTAGE - 1;
        if (tn < nt) load_stage(tn & (NSTAGE - 1), tn);
        cpa_commit();

        uint32_t aoff = sBase + (uint32_t)(t & (NSTAGE - 1)) * STAGE_B;
        uint32_t boff = aoff + A_HALF;
#pragma unroll
        for (int ks = 0; ks < 2; ks++) {
            uint32_t af[MT][4];
#pragma unroll
            for (int mt = 0; mt < MT; mt++)
                ldsm4(af[mt], aoff + ((wm + mt * 16 + lr) * GLDS + ks * 16 + lh * 8) * 2);
            uint32_t bf[2][4];
#pragma unroll
            for (int bt = 0; bt < 2; bt++)
                ldsm4(bf[bt], boff + ((wn + bt * 16 + lr) * GLDS + ks * 16 + lh * 8) * 2);
#pragma unroll
            for (int mt = 0; mt < MT; mt++) {
#pragma unroll
                for (int ntile = 0; ntile < 4; ntile++) {
                    int bt = ntile >> 1, sub = ntile & 1;
                    mma16816(acc[mt][ntile], af[mt], bf[bt][sub], bf[bt][sub + 2]);
                }
            }
        }
    }

    // epilogue: d0,d1 -> (m, n),(m, n+1); d2,d3 -> (m+8, n),(m+8, n+1)
    const int em = lane >> 2;
    const int en = (lane & 3) * 2;
#pragma unroll
    for (int mt = 0; mt < MT; mt++) {
#pragma unroll
        for (int ntile = 0; ntile < 4; ntile++) {
            int n = bn0 + wn + ntile * 8 + en;
            if (n >= Nreal) continue;
            int m = bm0 + wm + mt * 16 + em;
            float2 v0 = make_float2(acc[mt][ntile][0], acc[mt][ntile][1]);
            float2 v1 = make_float2(acc[mt][ntile][2], acc[mt][ntile][3]);
            if (bias) {
                float b0v = bias[n], b1v = bias[n + 1];
                v0.x += b0v; v0.y += b1v; v1.x += b0v; v1.y += b1v;
            }
            if (act == 1) {
                v0.x = softplusf(v0.x); v0.y = softplusf(v0.y);
                v1.x = softplusf(v1.x); v1.y = softplusf(v1.y);
            }
            *(float2*)(C + (size_t)m * ldc + n) = v0;
            *(float2*)(C + (size_t)(m + 8) * ldc + n) = v1;
            if (D2 && n < 48) {   // dt_low fp16x2 fused (A-side pattern)
                __half hi, lo;
                __half* p0 = D2 + (size_t)m * K2_DT;
                split2(v0.x, hi, lo); p0[n] = hi; p0[64 + n] = lo;
                split2(v0.y, hi, lo); p0[n+1] = hi; p0[64 + n+1] = lo;
                __half* p1 = D2 + (size_t)(m + 8) * K2_DT;
                split2(v1.x, hi, lo); p1[n] = hi; p1[64 + n] = lo;
                split2(v1.y, hi, lo); p1[n+1] = hi; p1[64 + n+1] = lo;
            }
        }
    }
}

// =============== causal depthwise conv + silu + fp16 double ==============
__global__ void conv_silu_kernel(const float* __restrict__ xz,
                                 const float* __restrict__ cw, const float* __restrict__ cb,
                                 const float* __restrict__ cwb, const float* __restrict__ cbb,
                                 float* __restrict__ xcf, float* __restrict__ xcbk,
                                 __half* __restrict__ xc2f,
                                 __half* __restrict__ xc2b)
{
    int idx = blockIdx.x * blockDim.x + threadIdx.x;
    if (idx >= TT * DI) return;
    int d = idx % DI;
    int t = (idx / DI) % LL;
    int b = idx / (DI * LL);
    const float* xb = xz + (size_t)b * LL * NXZ + d;     // xs part, ld = 3072

    float accf = cb[d];
    if (t >= 3) accf = fmaf(xb[(size_t)(t - 3) * NXZ], cw[d * 4 + 0], accf);
    if (t >= 2) accf = fmaf(xb[(size_t)(t - 2) * NXZ], cw[d * 4 + 1], accf);
    if (t >= 1) accf = fmaf(xb[(size_t)(t - 1) * NXZ], cw[d * 4 + 2], accf);
    accf = fmaf(xb[(size_t)t * NXZ], cw[d * 4 + 3], accf);
    float vf = siluf(accf);

    int base = (LL - 1) - t;
    float accb = cbb[d];
    if (t >= 3) accb = fmaf(xb[(size_t)(base + 3) * NXZ], cwb[d * 4 + 0], accb);
    if (t >= 2) accb = fmaf(xb[(size_t)(base + 2) * NXZ], cwb[d * 4 + 1], accb);
    if (t >= 1) accb = fmaf(xb[(size_t)(base + 1) * NXZ], cwb[d * 4 + 2], accb);
    accb = fmaf(xb[(size_t)base * NXZ], cwb[d * 4 + 3], accb);
    float vb = siluf(accb);

    size_t r = (size_t)(b * LL + t);
    xcf[r * DI + d] = vf;
    xcbk[r * DI + d] = vb;
    __half hi, lo;
    split2(vf, hi, lo);
    __half* d2 = xc2f + r * K2_BIG;
    d2[d] = hi; d2[DI + d] = lo;
    split2(vb, hi, lo);
    d2 = xc2b + r * K2_BIG;
    d2[d] = hi; d2[DI + d] = lo;
}

// ======================= selective scan ==================================
__global__ __launch_bounds__(256)
void scan_kernel(const float* __restrict__ xc0, const float* __restrict__ xc1,
                 const float* __restrict__ dl0, const float* __restrict__ dl1,
                 const float* __restrict__ pj0, const float* __restrict__ pj1,
                 const float* __restrict__ Alog0, const float* __restrict__ Alog1,
                 const float* __restrict__ Dp0, const float* __restrict__ Dp1,
                 float* __restrict__ y0, float* __restrict__ y1)
{
    int bid = blockIdx.x;
    int dgroup = bid % 96;
    int b = (bid / 96) % BB;
    int dir = bid / (96 * BB);

    const float* xc = dir ? xc1 : xc0;
    const float* dl = dir ? dl1 : dl0;
    const float* pj = dir ? pj1 : pj0;
    const float* Alog = dir ? Alog1 : Alog0;
    const float* Dp = dir ? Dp1 : Dp0;
    float* y = dir ? y1 : y0;

    int lane = threadIdx.x & 31;
    int w = threadIdx.x >> 5;
    int n = lane & 15;
    int d = dgroup * 16 + w * 2 + (lane >> 4);

    const float* xcp = xc + (size_t)b * LL * DI + d;
    const float* dlp = dl + (size_t)b * LL * DI + d;
    const float* pjB = pj + (size_t)b * LL * NPROJ + 48 + n;
    const float* pjC = pj + (size_t)b * LL * NPROJ + 64 + n;
    float* yp = y + (size_t)b * LL * DI + d;

    const float A = -__expf(Alog[d * DS + n]);
    const float Dd = Dp[d];

    float h = 0.0f;
    float dv = dlp[0], xv = xcp[0], Bv = pjB[0], Cv = pjC[0];

    for (int t = 0; t < LL; ++t) {
        float dv2 = 0.f, xv2 = 0.f, Bv2 = 0.f, Cv2 = 0.f;
        if (t + 1 < LL) {
            dv2 = dlp[(size_t)(t + 1) * DI];
            xv2 = xcp[(size_t)(t + 1) * DI];
            Bv2 = pjB[(size_t)(t + 1) * NPROJ];
            Cv2 = pjC[(size_t)(t + 1) * NPROJ];
        }
        float dA = __expf(dv * A);
        h = fmaf(dA, h, dv * xv * Bv);
        float p = h * Cv;
        p += __shfl_xor_sync(0xffffffffu, p, 1);
        p += __shfl_xor_sync(0xffffffffu, p, 2);
        p += __shfl_xor_sync(0xffffffffu, p, 4);
        p += __shfl_xor_sync(0xffffffffu, p, 8);
        if (n == 0) yp[(size_t)t * DI] = fmaf(Dd, xv, p);
        dv = dv2; xv = xv2; Bv = Bv2; Cv = Cv2;
    }
}

// ========== combine: 0.5*silu(z)*(y_f + rev(y_b)) -> fp16 double ==========
__global__ void combine_kernel(const float* __restrict__ xz,
                               const float* __restrict__ yf,
                               const float* __restrict__ yb,
                               __half* __restrict__ yc2)
{
    int idx = blockIdx.x * blockDim.x + threadIdx.x;
    if (idx >= TT * DI) return;
    int d = idx % DI;
    int l = (idx / DI) % LL;
    int b = idx / (DI * LL);
    float zz = xz[((size_t)b * LL + l) * NXZ + DI + d];
    float s = zz / (1.0f + __expf(-zz));
    float v = yf[idx] + yb[((size_t)b * LL + (LL - 1 - l)) * DI + d];
    v *= 0.5f * s;
    __half hi, lo; split2(v, hi, lo);
    __half* d2 = yc2 + (size_t)(b * LL + l) * K2_BIG;
    d2[d] = hi; d2[DI + d] = lo;
}

// ======================= launch ==========================================
extern "C" void kernel_launch(void* const* d_in, const int* in_sizes, int n_in,
                              void* d_out, int out_size)
{
    const float* x        = (const float*)d_in[0];
    const float* W_in_s   = (const float*)d_in[1];
    const float* W_in_g   = (const float*)d_in[2];
    const float* conv_w   = (const float*)d_in[3];
    const float* conv_b   = (const float*)d_in[4];
    const float* conv_w_b = (const float*)d_in[5];
    const float* conv_b_b = (const float*)d_in[6];
    const float* W_dt     = (const float*)d_in[7];
    const float* W_B      = (const float*)d_in[8];
    const float* W_C      = (const float*)d_in[9];
    const float* dtW      = (const float*)d_in[10];
    const float* dtb      = (const float*)d_in[11];
    const float* A_log    = (const float*)d_in[12];
    const float* Dp       = (const float*)d_in[13];
    const float* W_dt_b   = (const float*)d_in[14];
    const float* W_B_b    = (const float*)d_in[15];
    const float* W_C_b    = (const float*)d_in[16];
    const float* dtW_b    = (const float*)d_in[17];
    const float* dtb_b    = (const float*)d_in[18];
    const float* A_log_b  = (const float*)d_in[19];
    const float* Dp_b     = (const float*)d_in[20];
    const float* W_out    = (const float*)d_in[21];
    float* out = (float*)d_out;

    cudaFuncSetAttribute(gemm_mma, cudaFuncAttributeMaxDynamicSharedMemorySize, GSMEM);

    float *p_xz, *p_xc, *p_wp, *p_pj, *p_dl, *p_y;
    __half *p_x2, *p_Wcat2, *p_xc2, *p_wp2, *p_pj2, *p_dtW2, *p_yc2, *p_Wout2;
    cudaGetSymbolAddress((void**)&p_xz, g_xz);
    cudaGetSymbolAddress((void**)&p_x2, g_x2);
    cudaGetSymbolAddress((void**)&p_Wcat2, g_Wcat2);
    cudaGetSymbolAddress((void**)&p_xc, g_xc);
    cudaGetSymbolAddress((void**)&p_xc2, g_xc2);
    cudaGetSymbolAddress((void**)&p_wp, g_wproj);
    cudaGetSymbolAddress((void**)&p_wp2, g_wproj2);
    cudaGetSymbolAddress((void**)&p_pj, g_pj);
    cudaGetSymbolAddress((void**)&p_pj2, g_pj2);
    cudaGetSymbolAddress((void**)&p_dtW2, g_dtW2);
    cudaGetSymbolAddress((void**)&p_dl, g_delta);
    cudaGetSymbolAddress((void**)&p_y, g_y);
    cudaGetSymbolAddress((void**)&p_yc2, g_yc2);
    cudaGetSymbolAddress((void**)&p_Wout2, g_Wout2);

    float* xc0 = p_xc;  float* xc1 = p_xc + (size_t)TT * DI;
    float* pj0 = p_pj;  float* pj1 = p_pj + (size_t)TT * NPROJ;
    float* dl0 = p_dl;  float* dl1 = p_dl + (size_t)TT * DI;
    float* y0  = p_y;   float* y1  = p_y + (size_t)TT * DI;
    float* wp0 = p_wp;  float* wp1 = p_wp + (size_t)NPROJ * DI;
    __half* xc2f = p_xc2;
    __half* xc2b = p_xc2 + (size_t)TT * K2_BIG;
    __half* wp2f = p_wp2;
    __half* wp2b = p_wp2 + (size_t)NPROJ * K2_BIG;
    __half* pj2f = p_pj2;
    __half* pj2b = p_pj2 + (size_t)TT * K2_DT;
    __half* dtW2f = p_dtW2;
    __half* dtW2b = p_dtW2 + (size_t)DI * K2_DT;

    const int EW = 256;
    const int nEW = (TT * DI + EW - 1) / EW;
    auto cgrid = [](int total) { return (total + 255) / 256; };

    // --- in-proj prerequisites only, so the GEMM is OUR launch idx 3 ---
    conv2_kernel<<<cgrid(TT * DM), 256>>>(x, DM, DM, DM, p_x2, 1, TT * DM);
    conv2_kernel<<<cgrid(DI * DM), 256>>>(W_in_s, DM, DM, DM, p_Wcat2, 0, DI * DM);
    conv2_kernel<<<cgrid(DI * DM), 256>>>(W_in_g, DM, DM, DM,
                                          p_Wcat2 + (size_t)DI * K2_IN, 0, DI * DM);

    // in-proj: xz[T,3072] = x2 @ Wcat2^T          (our idx 3 — ncu capture)
    gemm_mma<<<dim3(NXZ / 128, TT / BM, 1), 256, GSMEM>>>(
        p_x2, p_x2, p_Wcat2, p_Wcat2, p_xz, p_xz, NXZ, K2_IN, NXZ,
        nullptr, nullptr, 0, nullptr, nullptr);

    // remaining weight prep (independent of in-proj)
    concat_wproj<<<cgrid(NPROJ * DI), 256>>>(W_dt, W_B, W_C, W_dt_b, W_B_b, W_C_b, wp0, wp1);
    prep_rest_kernel<<<1184, 256>>>(wp0, wp1, dtW, dtW_b, W_out,
                                    wp2f, wp2b, dtW2f, dtW2b, p_Wout2);

    // conv + silu + fp16 double
    conv_silu_kernel<<<nEW, EW>>>(p_xz, conv_w, conv_b, conv_w_b, conv_b_b,
                                  xc0, xc1, xc2f, xc2b);

    // proj: pj[T,80] = xc2 @ wproj2^T (both dirs) + fused pj2 double
    gemm_mma<<<dim3(1, TT / BM, 2), 256, GSMEM>>>(
        xc2f, xc2b, wp2f, wp2b, pj0, pj1, NPROJ, K2_BIG, NPROJ,
        nullptr, nullptr, 0, pj2f, pj2b);

    // delta = softplus(pj2 @ dtW2^T + dtb) (both dirs)
    gemm_mma<<<dim3(DI / 128, TT / BM, 2), 256, GSMEM>>>(
        pj2f, pj2b, dtW2f, dtW2b, dl0, dl1, DI, K2_DT, DI,
        dtb, dtb_b, 1, nullptr, nullptr);

    // selective scan
    scan_kernel<<<2 * BB * (DI / 16), 256>>>(
        xc0, xc1, dl0, dl1, pj0, pj1, A_log, A_log_b, Dp, Dp_b, y0, y1);

    // combine -> yc2 (fp16 double)
    combine_kernel<<<nEW, EW>>>(p_xz, y0, y1, p_yc2);

    // out-proj: out[T,768] = yc2 @ Wout2^T
    gemm_mma<<<dim3(DM / 128, TT / BM, 1), 256, GSMEM>>>(
        p_yc2, p_yc2, p_Wout2, p_Wout2, out, out, DM, K2_BIG, DM,
        nullptr, nullptr, 0, nullptr, nullptr);
}

// round 8
// speedup vs baseline: 1.5111x; 1.0584x over previous
#include <cuda_runtime.h>
#include <cuda_fp16.h>
#include <cstdint>
#include <cstddef>

#define DM 768
#define DI 1536
#define DS 16
#define DR 48
#define BB 2
#define LL 1024
#define TT (BB*LL)
#define NPROJ 80
#define NXZ 3072          // xs(1536) + z(1536) fused in-proj
#define K2_IN  1536       // 2*768
#define K2_BIG 3072       // 2*1536
#define K2_DT  128        // 2*64 (48 padded to 64)
#define SK_PJ 6           // split-K for proj GEMM
#define SK_OUT 3          // split-K for out-proj GEMM

// ======================= scratch (device globals) =======================
__device__ __align__(128) float g_xz[TT*NXZ];
__device__ __align__(128) __half g_x2[(size_t)TT*K2_IN];
__device__ __align__(128) __half g_Wcat2[(size_t)NXZ*K2_IN];
__device__ __align__(128) float g_xc[2][TT*DI];
__device__ __align__(128) __half g_xc2[2][(size_t)TT*K2_BIG];
__device__ __align__(128) float g_wproj[2][NPROJ*DI];
__device__ __align__(128) __half g_wproj2[2][(size_t)NPROJ*K2_BIG];
__device__ __align__(128) float g_pj[2][TT*NPROJ];
__device__ __align__(128) __half g_pj2[2][(size_t)TT*K2_DT];   // pad cols stay 0
__device__ __align__(128) __half g_dtW2[2][(size_t)DI*K2_DT];
__device__ __align__(128) float g_delta[2][TT*DI];
__device__ __align__(128) float g_y[2][TT*DI];
__device__ __align__(128) __half g_yc2[(size_t)TT*K2_BIG];
__device__ __align__(128) __half g_Wout2[(size_t)DM*K2_BIG];
__device__ __align__(128) float g_part[(size_t)SK_OUT*TT*DM];  // split-K partials

__device__ __forceinline__ float siluf(float x) { return x / (1.0f + __expf(-x)); }
__device__ __forceinline__ float softplusf(float x) {
    return (x > 20.0f) ? x : log1pf(__expf(x));
}
__device__ __forceinline__ void split2(float v, __half& hi, __half& lo) {
    hi = __float2half_rn(v);
    lo = __float2half_rn(v - __half2float(hi));
}

// =============== fp16-double conversion: fp32[rows,K] -> fp16[rows,2*Kseg]
// isA: segs {hi, lo};  !isA (B-side): segs {hi, hi}
__global__ void conv2_kernel(const float* __restrict__ src, int lds, int Kreal,
                             int Kseg, __half* __restrict__ dst, int isA,
                             int total)
{
    int idx = blockIdx.x * blockDim.x + threadIdx.x;
    if (idx >= total) return;
    int r = idx / Kseg, k = idx - r * Kseg;
    float v = (k < Kreal) ? src[(size_t)r * lds + k] : 0.0f;
    __half hi, lo; split2(v, hi, lo);
    size_t base = (size_t)r * 2 * Kseg;
    if (isA) { dst[base + k] = hi; dst[base + Kseg + k] = lo; }
    else     { dst[base + k] = hi; dst[base + Kseg + k] = hi; }
}

// =============== concat dt/B/C weights into [80,1536] per dir =============
__global__ void concat_wproj(const float* __restrict__ Wdt, const float* __restrict__ WB,
                             const float* __restrict__ WC,
                             const float* __restrict__ Wdtb, const float* __restrict__ WBb,
                             const float* __restrict__ WCb,
                             float* __restrict__ w0, float* __restrict__ w1)
{
    int i = blockIdx.x * blockDim.x + threadIdx.x;
    if (i >= NPROJ * DI) return;
    int r = i / DI, c = i % DI;
    float vf, vb;
    if (r < 48)      { vf = Wdt[r * DI + c];        vb = Wdtb[r * DI + c]; }
    else if (r < 64) { vf = WB[(r - 48) * DI + c];  vb = WBb[(r - 48) * DI + c]; }
    else             { vf = WC[(r - 64) * DI + c];  vb = WCb[(r - 64) * DI + c]; }
    w0[i] = vf; w1[i] = vb;
}

// =============== fused remaining weight conversions (B-side) ==============
#define RW0 (NPROJ*DI)
#define RW1 (2*NPROJ*DI)
#define RW2 (2*NPROJ*DI + DI*64)
#define RW3 (2*NPROJ*DI + 2*DI*64)
#define RWT (2*NPROJ*DI + 2*DI*64 + DM*DI)
__global__ void prep_rest_kernel(const float* __restrict__ wp0, const float* __restrict__ wp1,
                                 const float* __restrict__ dtW, const float* __restrict__ dtWb,
                                 const float* __restrict__ Wout,
                                 __half* __restrict__ wp2f, __half* __restrict__ wp2b,
                                 __half* __restrict__ dtW2f, __half* __restrict__ dtW2b,
                                 __half* __restrict__ Wout2)
{
    for (int idx = blockIdx.x * blockDim.x + threadIdx.x; idx < RWT;
         idx += gridDim.x * blockDim.x) {
        const float* src; __half* dst; int lds, Kreal, Kseg, local;
        if (idx < RW0)      { local = idx;       src = wp0;  dst = wp2f;  lds = DI; Kreal = DI; Kseg = DI; }
        else if (idx < RW1) { local = idx - RW0; src = wp1;  dst = wp2b;  lds = DI; Kreal = DI; Kseg = DI; }
        else if (idx < RW2) { local = idx - RW1; src = dtW;  dst = dtW2f; lds = DR; Kreal = DR; Kseg = 64; }
        else if (idx < RW3) { local = idx - RW2; src = dtWb; dst = dtW2b; lds = DR; Kreal = DR; Kseg = 64; }
        else                { local = idx - RW3; src = Wout; dst = Wout2; lds = DI; Kreal = DI; Kseg = DI; }
        int r = local / Kseg, k = local - r * Kseg;
        float v = (k < Kreal) ? src[(size_t)r * lds + k] : 0.0f;
        __half hi, lo; split2(v, hi, lo);
        size_t base = (size_t)r * 2 * Kseg;
        dst[base + k] = hi; dst[base + Kseg + k] = hi;
    }
}

// ======================= mma.sync fp16 NT GEMM (cp.async 4-stage) =========
// blockIdx.z = z*splitk + sk; each sk handles K-range [sk*K2/splitk, ...).
// splitk>1: raw fp32 partials to P[blockIdx.z][M][ldc] (deterministic reduce later)
#define BM 64
#define GBK 32
#define GLDS 40
#define NSTAGE 4
#define A_HALF (BM*80)
#define STAGE_B (A_HALF + 128*80)
#define GSMEM (NSTAGE*STAGE_B)
#define MT 2

__device__ __forceinline__ void ldsm4(uint32_t* r, uint32_t addr) {
    asm volatile("ldmatrix.sync.aligned.m8n8.x4.shared.b16 {%0,%1,%2,%3}, [%4];"
                 : "=r"(r[0]), "=r"(r[1]), "=r"(r[2]), "=r"(r[3]) : "r"(addr));
}
__device__ __forceinline__ void mma16816(float* d, const uint32_t* a,
                                         uint32_t b0, uint32_t b1) {
    asm volatile("mma.sync.aligned.m16n8k16.row.col.f32.f16.f16.f32 "
                 "{%0,%1,%2,%3}, {%4,%5,%6,%7}, {%8,%9}, {%0,%1,%2,%3};"
                 : "+f"(d[0]), "+f"(d[1]), "+f"(d[2]), "+f"(d[3])
                 : "r"(a[0]), "r"(a[1]), "r"(a[2]), "r"(a[3]), "r"(b0), "r"(b1));
}
__device__ __forceinline__ void cpa16(uint32_t dst, const void* src, int sz) {
    asm volatile("cp.async.cg.shared.global [%0], [%1], 16, %2;"
                 :: "r"(dst), "l"(src), "r"(sz) : "memory");
}
__device__ __forceinline__ void cpa_commit() {
    asm volatile("cp.async.commit_group;" ::: "memory");
}
__device__ __forceinline__ void cpa_wait2() {
    asm volatile("cp.async.wait_group 2;" ::: "memory");
}

__global__ __launch_bounds__(256, 3)
void gemm_mma(const __half* __restrict__ A0, const __half* __restrict__ A1,
              const __half* __restrict__ B0, const __half* __restrict__ B1,
              float* __restrict__ C0, float* __restrict__ C1,
              int ldc, int K2, int Nreal,
              const float* __restrict__ bias0, const float* __restrict__ bias1, int act,
              __half* __restrict__ D20, __half* __restrict__ D21,
              int splitk, float* __restrict__ P)
{
    extern __shared__ char smem[];

    const int zall = blockIdx.z;
    const int z = zall / splitk;
    const int sk = zall - z * splitk;
    const int K2eff = K2 / splitk;
    const int kbase = sk * K2eff;

    const __half* A = z ? A1 : A0;
    const __half* B = z ? B1 : B0;

    const int tid = threadIdx.x;
    const int lane = tid & 31;
    const int wid = tid >> 5;
    const int bm0 = blockIdx.y * BM;
    const int bn0 = blockIdx.x * 128;
    const int wm = (wid >> 2) * 32;
    const int wn = (wid & 3) * 32;

    const uint32_t sBase = (uint32_t)__cvta_generic_to_shared(smem);
    const int lr = lane & 15, lh = lane >> 4;

    float acc[MT][4][4];
#pragma unroll
    for (int i = 0; i < MT; i++)
#pragma unroll
        for (int j = 0; j < 4; j++)
#pragma unroll
            for (int v = 0; v < 4; v++) acc[i][j][v] = 0.0f;

    const int nt = K2eff / GBK;

    const int arow = tid >> 2, ach = tid & 3;
    const __half* Ap = A + (size_t)(bm0 + arow) * K2 + kbase + ach * 8;
    const int brow0 = bn0 + arow;
    const int brow1 = bn0 + arow + 64;
    const int bsz0 = (brow0 < Nreal) ? 16 : 0;
    const int bsz1 = (brow1 < Nreal) ? 16 : 0;
    const __half* Bp0 = B + (size_t)((brow0 < Nreal) ? brow0 : 0) * K2 + kbase + ach * 8;
    const __half* Bp1 = B + (size_t)((brow1 < Nreal) ? brow1 : 0) * K2 + kbase + ach * 8;
    const uint32_t sA = (uint32_t)(arow * 80 + ach * 16);
    const uint32_t sB0 = A_HALF + sA;
    const uint32_t sB1 = A_HALF + sA + 64 * 80;

    auto load_stage = [&](int s, int t) {
        uint32_t sb = sBase + (uint32_t)s * STAGE_B;
        size_t koff = (size_t)t * GBK;
        cpa16(sb + sA, Ap + koff, 16);
        cpa16(sb + sB0, Bp0 + koff, bsz0);
        cpa16(sb + sB1, Bp1 + koff, bsz1);
    };

#pragma unroll
    for (int s = 0; s < NSTAGE - 1; s++) {
        if (s < nt) load_stage(s, s);
        cpa_commit();
    }

    for (int t = 0; t < nt; t++) {
        cpa_wait2();
        __syncthreads();

        int tn = t + NSTAGE - 1;
        if (tn < nt) load_stage(tn & (NSTAGE - 1), tn);
        cpa_commit();

        uint32_t aoff = sBase + (uint32_t)(t & (NSTAGE - 1)) * STAGE_B;
        uint32_t boff = aoff + A_HALF;
#pragma unroll
        for (int ks = 0; ks < 2; ks++) {
            uint32_t af[MT][4];
#pragma unroll
            for (int mt = 0; mt < MT; mt++)
                ldsm4(af[mt], aoff + ((wm + mt * 16 + lr) * GLDS + ks * 16 + lh * 8) * 2);
            uint32_t bf[2][4];
#pragma unroll
            for (int bt = 0; bt < 2; bt++)
                ldsm4(bf[bt], boff + ((wn + bt * 16 + lr) * GLDS + ks * 16 + lh * 8) * 2);
#pragma unroll
            for (int mt = 0; mt < MT; mt++) {
#pragma unroll
                for (int ntile = 0; ntile < 4; ntile++) {
                    int bt = ntile >> 1, sub = ntile & 1;
                    mma16816(acc[mt][ntile], af[mt], bf[bt][sub], bf[bt][sub + 2]);
                }
            }
        }
    }

    const int em = lane >> 2;
    const int en = (lane & 3) * 2;

    if (splitk > 1) {
        // raw partial store: P[zall][m][n], ldc row stride
        float* Cp = P + (size_t)zall * TT * ldc;
#pragma unroll
        for (int mt = 0; mt < MT; mt++) {
#pragma unroll
            for (int ntile = 0; ntile < 4; ntile++) {
                int n = bn0 + wn + ntile * 8 + en;
                if (n >= Nreal) continue;
                int m = bm0 + wm + mt * 16 + em;
                *(float2*)(Cp + (size_t)m * ldc + n) =
                    make_float2(acc[mt][ntile][0], acc[mt][ntile][1]);
                *(float2*)(Cp + (size_t)(m + 8) * ldc + n) =
                    make_float2(acc[mt][ntile][2], acc[mt][ntile][3]);
            }
        }
        return;
    }

    float* C = z ? C1 : C0;
    const float* bias = z ? bias1 : bias0;
    __half* D2 = z ? D21 : D20;
#pragma unroll
    for (int mt = 0; mt < MT; mt++) {
#pragma unroll
        for (int ntile = 0; ntile < 4; ntile++) {
            int n = bn0 + wn + ntile * 8 + en;
            if (n >= Nreal) continue;
            int m = bm0 + wm + mt * 16 + em;
            float2 v0 = make_float2(acc[mt][ntile][0], acc[mt][ntile][1]);
            float2 v1 = make_float2(acc[mt][ntile][2], acc[mt][ntile][3]);
            if (bias) {
                float b0v = bias[n], b1v = bias[n + 1];
                v0.x += b0v; v0.y += b1v; v1.x += b0v; v1.y += b1v;
            }
            if (act == 1) {
                v0.x = softplusf(v0.x); v0.y = softplusf(v0.y);
                v1.x = softplusf(v1.x); v1.y = softplusf(v1.y);
            }
            *(float2*)(C + (size_t)m * ldc + n) = v0;
            *(float2*)(C + (size_t)(m + 8) * ldc + n) = v1;
            if (D2 && n < 48) {
                __half hi, lo;
                __half* p0 = D2 + (size_t)m * K2_DT;
                split2(v0.x, hi, lo); p0[n] = hi; p0[64 + n] = lo;
                split2(v0.y, hi, lo); p0[n+1] = hi; p0[64 + n+1] = lo;
                __half* p1 = D2 + (size_t)(m + 8) * K2_DT;
                split2(v1.x, hi, lo); p1[n] = hi; p1[64 + n] = lo;
                split2(v1.y, hi, lo); p1[n+1] = hi; p1[64 + n+1] = lo;
            }
        }
    }
}

// ====== proj split-K reduce (fixed order, deterministic) + pj2 fusion =====
__global__ void reduce_proj_kernel(const float* __restrict__ P,
                                   float* __restrict__ pj0, float* __restrict__ pj1,
                                   __half* __restrict__ pj2f, __half* __restrict__ pj2b)
{
    int idx = blockIdx.x * blockDim.x + threadIdx.x;
    if (idx >= 2 * TT * NPROJ) return;
    int dir = idx / (TT * NPROJ);
    int rem = idx - dir * TT * NPROJ;
    int m = rem / NPROJ, n = rem - m * NPROJ;
    const float* base = P + (size_t)dir * SK_PJ * TT * NPROJ + (size_t)m * NPROJ + n;
    float s = 0.0f;
#pragma unroll
    for (int sk = 0; sk < SK_PJ; sk++) s += base[(size_t)sk * TT * NPROJ];
    (dir ? pj1 : pj0)[(size_t)m * NPROJ + n] = s;
    if (n < 48) {
        __half hi, lo; split2(s, hi, lo);
        __half* p2 = (dir ? pj2b : pj2f) + (size_t)m * K2_DT;
        p2[n] = hi; p2[64 + n] = lo;
    }
}

// ====== out split-K reduce (fixed order, deterministic) ====================
__global__ void reduce_out_kernel(const float* __restrict__ P, float* __restrict__ out)
{
    int idx = blockIdx.x * blockDim.x + threadIdx.x;
    if (idx >= TT * DM) return;
    out[idx] = P[idx] + P[(size_t)TT * DM + idx] + P[(size_t)2 * TT * DM + idx];
}

// =============== causal depthwise conv + silu + fp16 double ==============
__global__ void conv_silu_kernel(const float* __restrict__ xz,
                                 const float* __restrict__ cw, const float* __restrict__ cb,
                                 const float* __restrict__ cwb, const float* __restrict__ cbb,
                                 float* __restrict__ xcf, float* __restrict__ xcbk,
                                 __half* __restrict__ xc2f,
                                 __half* __restrict__ xc2b)
{
    int idx = blockIdx.x * blockDim.x + threadIdx.x;
    if (idx >= TT * DI) return;
    int d = idx % DI;
    int t = (idx / DI) % LL;
    int b = idx / (DI * LL);
    const float* xb = xz + (size_t)b * LL * NXZ + d;

    float accf = cb[d];
    if (t >= 3) accf = fmaf(xb[(size_t)(t - 3) * NXZ], cw[d * 4 + 0], accf);
    if (t >= 2) accf = fmaf(xb[(size_t)(t - 2) * NXZ], cw[d * 4 + 1], accf);
    if (t >= 1) accf = fmaf(xb[(size_t)(t - 1) * NXZ], cw[d * 4 + 2], accf);
    accf = fmaf(xb[(size_t)t * NXZ], cw[d * 4 + 3], accf);
    float vf = siluf(accf);

    int base = (LL - 1) - t;
    float accb = cbb[d];
    if (t >= 3) accb = fmaf(xb[(size_t)(base + 3) * NXZ], cwb[d * 4 + 0], accb);
    if (t >= 2) accb = fmaf(xb[(size_t)(base + 2) * NXZ], cwb[d * 4 + 1], accb);
    if (t >= 1) accb = fmaf(xb[(size_t)(base + 1) * NXZ], cwb[d * 4 + 2], accb);
    accb = fmaf(xb[(size_t)base * NXZ], cwb[d * 4 + 3], accb);
    float vb = siluf(accb);

    size_t r = (size_t)(b * LL + t);
    xcf[r * DI + d] = vf;
    xcbk[r * DI + d] = vb;
    __half hi, lo;
    split2(vf, hi, lo);
    __half* d2 = xc2f + r * K2_BIG;
    d2[d] = hi; d2[DI + d] = lo;
    split2(vb, hi, lo);
    d2 = xc2b + r * K2_BIG;
    d2[d] = hi; d2[DI + d] = lo;
}

// ======================= selective scan ==================================
__global__ __launch_bounds__(256)
void scan_kernel(const float* __restrict__ xc0, const float* __restrict__ xc1,
                 const float* __restrict__ dl0, const float* __restrict__ dl1,
                 const float* __restrict__ pj0, const float* __restrict__ pj1,
                 const float* __restrict__ Alog0, const float* __restrict__ Alog1,
                 const float* __restrict__ Dp0, const float* __restrict__ Dp1,
                 float* __restrict__ y0, float* __restrict__ y1)
{
    int bid = blockIdx.x;
    int dgroup = bid % 96;
    int b = (bid / 96) % BB;
    int dir = bid / (96 * BB);

    const float* xc = dir ? xc1 : xc0;
    const float* dl = dir ? dl1 : dl0;
    const float* pj = dir ? pj1 : pj0;
    const float* Alog = dir ? Alog1 : Alog0;
    const float* Dp = dir ? Dp1 : Dp0;
    float* y = dir ? y1 : y0;

    int lane = threadIdx.x & 31;
    int w = threadIdx.x >> 5;
    int n = lane & 15;
    int d = dgroup * 16 + w * 2 + (lane >> 4);

    const float* xcp = xc + (size_t)b * LL * DI + d;
    const float* dlp = dl + (size_t)b * LL * DI + d;
    const float* pjB = pj + (size_t)b * LL * NPROJ + 48 + n;
    const float* pjC = pj + (size_t)b * LL * NPROJ + 64 + n;
    float* yp = y + (size_t)b * LL * DI + d;

    const float A = -__expf(Alog[d * DS + n]);
    const float Dd = Dp[d];

    float h = 0.0f;
    float dv = dlp[0], xv = xcp[0], Bv = pjB[0], Cv = pjC[0];

    for (int t = 0; t < LL; ++t) {
        float dv2 = 0.f, xv2 = 0.f, Bv2 = 0.f, Cv2 = 0.f;
        if (t + 1 < LL) {
            dv2 = dlp[(size_t)(t + 1) * DI];
            xv2 = xcp[(size_t)(t + 1) * DI];
            Bv2 = pjB[(size_t)(t + 1) * NPROJ];
            Cv2 = pjC[(size_t)(t + 1) * NPROJ];
        }
        float dA = __expf(dv * A);
        h = fmaf(dA, h, dv * xv * Bv);
        float p = h * Cv;
        p += __shfl_xor_sync(0xffffffffu, p, 1);
        p += __shfl_xor_sync(0xffffffffu, p, 2);
        p += __shfl_xor_sync(0xffffffffu, p, 4);
        p += __shfl_xor_sync(0xffffffffu, p, 8);
        if (n == 0) yp[(size_t)t * DI] = fmaf(Dd, xv, p);
        dv = dv2; xv = xv2; Bv = Bv2; Cv = Cv2;
    }
}

// ========== combine: 0.5*silu(z)*(y_f + rev(y_b)) -> fp16 double ==========
__global__ void combine_kernel(const float* __restrict__ xz,
                               const float* __restrict__ yf,
                               const float* __restrict__ yb,
                               __half* __restrict__ yc2)
{
    int idx = blockIdx.x * blockDim.x + threadIdx.x;
    if (idx >= TT * DI) return;
    int d = idx % DI;
    int l = (idx / DI) % LL;
    int b = idx / (DI * LL);
    float zz = xz[((size_t)b * LL + l) * NXZ + DI + d];
    float s = zz / (1.0f + __expf(-zz));
    float v = yf[idx] + yb[((size_t)b * LL + (LL - 1 - l)) * DI + d];
    v *= 0.5f * s;
    __half hi, lo; split2(v, hi, lo);
    __half* d2 = yc2 + (size_t)(b * LL + l) * K2_BIG;
    d2[d] = hi; d2[DI + d] = lo;
}

// ======================= launch ==========================================
extern "C" void kernel_launch(void* const* d_in, const int* in_sizes, int n_in,
                              void* d_out, int out_size)
{
    const float* x        = (const float*)d_in[0];
    const float* W_in_s   = (const float*)d_in[1];
    const float* W_in_g   = (const float*)d_in[2];
    const float* conv_w   = (const float*)d_in[3];
    const float* conv_b   = (const float*)d_in[4];
    const float* conv_w_b = (const float*)d_in[5];
    const float* conv_b_b = (const float*)d_in[6];
    const float* W_dt     = (const float*)d_in[7];
    const float* W_B      = (const float*)d_in[8];
    const float* W_C      = (const float*)d_in[9];
    const float* dtW      = (const float*)d_in[10];
    const float* dtb      = (const float*)d_in[11];
    const float* A_log    = (const float*)d_in[12];
    const float* Dp       = (const float*)d_in[13];
    const float* W_dt_b   = (const float*)d_in[14];
    const float* W_B_b    = (const float*)d_in[15];
    const float* W_C_b    = (const float*)d_in[16];
    const float* dtW_b    = (const float*)d_in[17];
    const float* dtb_b    = (const float*)d_in[18];
    const float* A_log_b  = (const float*)d_in[19];
    const float* Dp_b     = (const float*)d_in[20];
    const float* W_out    = (const float*)d_in[21];
    float* out = (float*)d_out;

    cudaFuncSetAttribute(gemm_mma, cudaFuncAttributeMaxDynamicSharedMemorySize, GSMEM);

    float *p_xz, *p_xc, *p_wp, *p_pj, *p_dl, *p_y, *p_part;
    __half *p_x2, *p_Wcat2, *p_xc2, *p_wp2, *p_pj2, *p_dtW2, *p_yc2, *p_Wout2;
    cudaGetSymbolAddress((void**)&p_xz, g_xz);
    cudaGetSymbolAddress((void**)&p_x2, g_x2);
    cudaGetSymbolAddress((void**)&p_Wcat2, g_Wcat2);
    cudaGetSymbolAddress((void**)&p_xc, g_xc);
    cudaGetSymbolAddress((void**)&p_xc2, g_xc2);
    cudaGetSymbolAddress((void**)&p_wp, g_wproj);
    cudaGetSymbolAddress((void**)&p_wp2, g_wproj2);
    cudaGetSymbolAddress((void**)&p_pj, g_pj);
    cudaGetSymbolAddress((void**)&p_pj2, g_pj2);
    cudaGetSymbolAddress((void**)&p_dtW2, g_dtW2);
    cudaGetSymbolAddress((void**)&p_dl, g_delta);
    cudaGetSymbolAddress((void**)&p_y, g_y);
    cudaGetSymbolAddress((void**)&p_yc2, g_yc2);
    cudaGetSymbolAddress((void**)&p_Wout2, g_Wout2);
    cudaGetSymbolAddress((void**)&p_part, g_part);

    float* xc0 = p_xc;  float* xc1 = p_xc + (size_t)TT * DI;
    float* pj0 = p_pj;  float* pj1 = p_pj + (size_t)TT * NPROJ;
    float* dl0 = p_dl;  float* dl1 = p_dl + (size_t)TT * DI;
    float* y0  = p_y;   float* y1  = p_y + (size_t)TT * DI;
    float* wp0 = p_wp;  float* wp1 = p_wp + (size_t)NPROJ * DI;
    __half* xc2f = p_xc2;
    __half* xc2b = p_xc2 + (size_t)TT * K2_BIG;
    __half* wp2f = p_wp2;
    __half* wp2b = p_wp2 + (size_t)NPROJ * K2_BIG;
    __half* pj2f = p_pj2;
    __half* pj2b = p_pj2 + (size_t)TT * K2_DT;
    __half* dtW2f = p_dtW2;
    __half* dtW2b = p_dtW2 + (size_t)DI * K2_DT;

    const int EW = 256;
    const int nEW = (TT * DI + EW - 1) / EW;
    auto cgrid = [](int total) { return (total + 255) / 256; };

    // --- in-proj prerequisites only (GEMM stays at our launch idx 3) ---
    conv2_kernel<<<cgrid(TT * DM), 256>>>(x, DM, DM, DM, p_x2, 1, TT * DM);
    conv2_kernel<<<cgrid(DI * DM), 256>>>(W_in_s, DM, DM, DM, p_Wcat2, 0, DI * DM);
    conv2_kernel<<<cgrid(DI * DM), 256>>>(W_in_g, DM, DM, DM,
                                          p_Wcat2 + (size_t)DI * K2_IN, 0, DI * DM);

    // in-proj: xz[T,3072] = x2 @ Wcat2^T
    gemm_mma<<<dim3(NXZ / 128, TT / BM, 1), 256, GSMEM>>>(
        p_x2, p_x2, p_Wcat2, p_Wcat2, p_xz, p_xz, NXZ, K2_IN, NXZ,
        nullptr, nullptr, 0, nullptr, nullptr, 1, nullptr);

    // remaining weight prep
    concat_wproj<<<cgrid(NPROJ * DI), 256>>>(W_dt, W_B, W_C, W_dt_b, W_B_b, W_C_b, wp0, wp1);
    prep_rest_kernel<<<1184, 256>>>(wp0, wp1, dtW, dtW_b, W_out,
                                    wp2f, wp2b, dtW2f, dtW2b, p_Wout2);

    // conv + silu + fp16 double
    conv_silu_kernel<<<nEW, EW>>>(p_xz, conv_w, conv_b, conv_w_b, conv_b_b,
                                  xc0, xc1, xc2f, xc2b);

    // proj: split-K=6 partials (both dirs) -> reduce (+ fused pj2)
    gemm_mma<<<dim3(1, TT / BM, 2 * SK_PJ), 256, GSMEM>>>(
        xc2f, xc2b, wp2f, wp2b, nullptr, nullptr, NPROJ, K2_BIG, NPROJ,
        nullptr, nullptr, 0, nullptr, nullptr, SK_PJ, p_part);
    reduce_proj_kernel<<<cgrid(2 * TT * NPROJ), 256>>>(p_part, pj0, pj1, pj2f, pj2b);

    // delta = softplus(pj2 @ dtW2^T + dtb) (both dirs, splitk=1)
    gemm_mma<<<dim3(DI / 128, TT / BM, 2), 256, GSMEM>>>(
        pj2f, pj2b, dtW2f, dtW2b, dl0, dl1, DI, K2_DT, DI,
        dtb, dtb_b, 1, nullptr, nullptr, 1, nullptr);

    // selective scan
    scan_kernel<<<2 * BB * (DI / 16), 256>>>(
        xc0, xc1, dl0, dl1, pj0, pj1, A_log, A_log_b, Dp, Dp_b, y0, y1);

    // combine -> yc2 (fp16 double)
    combine_kernel<<<nEW, EW>>>(p_xz, y0, y1, p_yc2);

    // out-proj: split-K=3 partials -> reduce
    gemm_mma<<<dim3(DM / 128, TT / BM, SK_OUT), 256, GSMEM>>>(
        p_yc2, p_yc2, p_Wout2, p_Wout2, nullptr, nullptr, DM, K2_BIG, DM,
        nullptr, nullptr, 0, nullptr, nullptr, SK_OUT, p_part);
    reduce_out_kernel<<<cgrid(TT * DM), 256>>>(p_part, out);
}